// round 13
// baseline (speedup 1.0000x reference)
#include <cuda_runtime.h>
#include <cuda_fp16.h>
#include <cstdint>

#define B_ 4
#define L_ 2048
#define D_ 512
#define H_ 8
#define DH_ 64
#define OUT_ELEMS (B_ * L_ * D_)          // 4194304
#define LOG2E_DIV32 0.04507129744f         // log2(e)/32

// Scratch (__device__ globals; allocation-free rule)
__device__ __half   g_qin[OUT_ELEMS];               // fp16 inputs
__device__ __half   g_kin[OUT_ELEMS];
__device__ __half   g_vin[OUT_ELEMS];
__device__ __half   g_wq[D_ * D_], g_wk[D_ * D_], g_wv[D_ * D_], g_wo[D_ * D_];
__device__ __half   g_qh[OUT_ELEMS];                // fp16 projections
__device__ __half   g_kh[OUT_ELEMS];
__device__ __half   g_vh[OUT_ELEMS];
__device__ __half   g_ctxh[OUT_ELEMS];              // fp16 attention context
__device__ float    g_inv[B_ * H_ * L_];
__device__ uint32_t g_maskb[(size_t)B_ * L_ * L_ / 32];   // 2 MB bitmask
__device__ __half   g_eh[(size_t)B_ * H_ * L_ * L_];      // 268 MB unnormalized e

// ---------------------------------------------------------------------------
// helpers
// ---------------------------------------------------------------------------
__device__ __forceinline__ void mma_f16(float4& d, uint32_t a0, uint32_t a1,
                                        uint32_t a2, uint32_t a3,
                                        uint32_t b0, uint32_t b1) {
    asm volatile(
        "mma.sync.aligned.m16n8k16.row.col.f32.f16.f16.f32 "
        "{%0,%1,%2,%3}, {%4,%5,%6,%7}, {%8,%9}, {%0,%1,%2,%3};"
        : "+f"(d.x), "+f"(d.y), "+f"(d.z), "+f"(d.w)
        : "r"(a0), "r"(a1), "r"(a2), "r"(a3), "r"(b0), "r"(b1));
}
__device__ __forceinline__ void ldsm4(uint32_t& r0, uint32_t& r1, uint32_t& r2,
                                      uint32_t& r3, uint32_t addr) {
    asm volatile("ldmatrix.sync.aligned.m8n8.x4.shared.b16 {%0,%1,%2,%3}, [%4];"
                 : "=r"(r0), "=r"(r1), "=r"(r2), "=r"(r3) : "r"(addr));
}
__device__ __forceinline__ void ldsm4t(uint32_t& r0, uint32_t& r1, uint32_t& r2,
                                       uint32_t& r3, uint32_t addr) {
    asm volatile("ldmatrix.sync.aligned.m8n8.x4.trans.shared.b16 {%0,%1,%2,%3}, [%4];"
                 : "=r"(r0), "=r"(r1), "=r"(r2), "=r"(r3) : "r"(addr));
}
__device__ __forceinline__ void cpa16(uint32_t s, const void* g) {
    asm volatile("cp.async.cg.shared.global [%0], [%1], 16;" :: "r"(s), "l"(g));
}
__device__ __forceinline__ void cpcommit() {
    asm volatile("cp.async.commit_group;" ::: "memory");
}
template <int N> __device__ __forceinline__ void cpwait() {
    asm volatile("cp.async.wait_group %0;" :: "n"(N) : "memory");
}

// ---------------------------------------------------------------------------
// prep: mask -> bitmask (warp ballot) + all fp32->fp16 converts.
// Segments: [0,2048) bitpack | [2048,14336) Q,K,V | [14336,15360) weights
// ---------------------------------------------------------------------------
__global__ __launch_bounds__(256)
void prep(const int* __restrict__ m,
          const float* __restrict__ Q, const float* __restrict__ K,
          const float* __restrict__ V, const float* __restrict__ Wq,
          const float* __restrict__ Wk, const float* __restrict__ Wv,
          const float* __restrict__ Wo) {
    int bx = blockIdx.x;
    if (bx < 2048) {
        // each warp packs 1024 ints -> 32 uint32 words
        const int wg = bx * 8 + (threadIdx.x >> 5);
        const int lane = threadIdx.x & 31;
        const size_t base = (size_t)wg * 1024;
        uint32_t word = 0;
#pragma unroll
        for (int r = 0; r < 32; r++) {
            const int v = m[base + (size_t)r * 32 + lane];
            const unsigned bits = __ballot_sync(0xffffffffu, v != 0);
            if (lane == r) word = bits;
        }
        g_maskb[base / 32 + lane] = word;
        return;
    }
    bx -= 2048;
    const float* s;
    __half* d;
    size_t i;
    if (bx < 3 * 4096) {
        const int seg = bx >> 12;
        const int b2 = bx & 4095;
        s = (seg == 0) ? Q : (seg == 1) ? K : V;
        d = (seg == 0) ? g_qin : (seg == 1) ? g_kin : g_vin;
        i = (size_t)b2 * 256 + threadIdx.x;
    } else {
        bx -= 3 * 4096;
        const int seg = bx >> 8;
        const int b2 = bx & 255;
        s = (seg == 0) ? Wq : (seg == 1) ? Wk : (seg == 2) ? Wv : Wo;
        d = (seg == 0) ? g_wq : (seg == 1) ? g_wk : (seg == 2) ? g_wv : g_wo;
        i = (size_t)b2 * 256 + threadIdx.x;
    }
    const float4 v = reinterpret_cast<const float4*>(s)[i];
    __half2 h0 = __floats2half2_rn(v.x, v.y);
    __half2 h1 = __floats2half2_rn(v.z, v.w);
    uint2 o;
    o.x = *(uint32_t*)&h0;
    o.y = *(uint32_t*)&h1;
    reinterpret_cast<uint2*>(d)[i] = o;
}

// ---------------------------------------------------------------------------
// fp16 GEMM body: C[M,512] = A[M,512] @ W[512,512] + bias (fp32 accum/bias).
// Block 128x64 via (blockIdx.x, blockIdx.y), 8 warps, warp 32x32, k-stage 64.
// ---------------------------------------------------------------------------
__device__ __forceinline__ void hgemm_issue(const __half* A, const __half* W,
                                            int m0, int n0, uint32_t as_s,
                                            uint32_t bs_s, int ki, int buf,
                                            int tid) {
    const __half* Ap = A + (size_t)m0 * 512 + ki * 64;
#pragma unroll
    for (int t = 0; t < 4; t++) {
        const int s = tid + 256 * t;
        const int r = s >> 3, c = (s & 7) << 3;
        cpa16(as_s + (uint32_t)((buf * 128 * 72 + r * 72 + c) * 2),
              Ap + (size_t)r * 512 + c);
    }
    const __half* Wp = W + (size_t)ki * 64 * 512 + n0;
#pragma unroll
    for (int t = 0; t < 2; t++) {
        const int s = tid + 256 * t;
        const int r = s >> 3, c = (s & 7) << 3;
        cpa16(bs_s + (uint32_t)((buf * 64 * 72 + r * 72 + c) * 2),
              Wp + (size_t)r * 512 + c);
    }
    cpcommit();
}

template <typename OutT>
__device__ __forceinline__ void hgemm_body(const __half* __restrict__ A,
                                           const __half* __restrict__ W,
                                           const float* __restrict__ bias,
                                           OutT* __restrict__ C) {
    extern __shared__ __half smh[];
    __half* Ah = smh;                  // [2][128][72]
    __half* Wh = smh + 2 * 128 * 72;   // [2][64][72]

    const int tid = threadIdx.x, l = tid & 31, w = tid >> 5;
    const int mg = w >> 1, ng = w & 1;
    const int wm = mg * 32, wn = ng * 32;
    const int lr = l >> 2, lc = l & 3;
    const int m0 = blockIdx.y << 7, n0 = blockIdx.x << 6;

    const uint32_t as_s = (uint32_t)__cvta_generic_to_shared(Ah);
    const uint32_t bs_s = (uint32_t)__cvta_generic_to_shared(Wh);

    const int a_row = (l & 15), a_col = (l >> 4) << 3;
    const int vb_row = (((l >> 3) & 1) << 3) + (l & 7);
    const int vb_col = (l >> 4) << 3;

    float4 acc[2][4];
#pragma unroll
    for (int m = 0; m < 2; m++)
#pragma unroll
        for (int j = 0; j < 4; j++) acc[m][j] = make_float4(0.f, 0.f, 0.f, 0.f);

    hgemm_issue(A, W, m0, n0, as_s, bs_s, 0, 0, tid);

    for (int ki = 0; ki < 8; ki++) {
        if (ki + 1 < 8) {
            hgemm_issue(A, W, m0, n0, as_s, bs_s, ki + 1, (ki + 1) & 1, tid);
            cpwait<1>();
        } else {
            cpwait<0>();
        }
        __syncthreads();

        const int buf = ki & 1;
        const uint32_t a0b = as_s + (uint32_t)((buf * 128 * 72 + (wm + a_row) * 72 + a_col) * 2);
        const uint32_t a1b = a0b + 16 * 72 * 2;
        const uint32_t wb = bs_s + (uint32_t)((buf * 64 * 72) * 2);

#pragma unroll
        for (int kc = 0; kc < 4; kc++) {
            uint32_t a0[4], a1[4];
            ldsm4(a0[0], a0[1], a0[2], a0[3], a0b + kc * 32);
            ldsm4(a1[0], a1[1], a1[2], a1[3], a1b + kc * 32);
#pragma unroll
            for (int j = 0; j < 2; j++) {
                uint32_t b0, b1, b2, b3;
                ldsm4t(b0, b1, b2, b3,
                       wb + (uint32_t)(((kc * 16 + vb_row) * 72 + wn + 16 * j + vb_col) * 2));
                mma_f16(acc[0][2 * j],     a0[0], a0[1], a0[2], a0[3], b0, b1);
                mma_f16(acc[1][2 * j],     a1[0], a1[1], a1[2], a1[3], b0, b1);
                mma_f16(acc[0][2 * j + 1], a0[0], a0[1], a0[2], a0[3], b2, b3);
                mma_f16(acc[1][2 * j + 1], a1[0], a1[1], a1[2], a1[3], b2, b3);
            }
        }
        __syncthreads();
    }

#pragma unroll
    for (int m = 0; m < 2; m++)
#pragma unroll
        for (int j = 0; j < 4; j++) {
            const int rg = m0 + wm + 16 * m + lr;
            const int cg = n0 + wn + 8 * j + 2 * lc;
            const float2 bv = *(const float2*)&bias[cg];
            if constexpr (sizeof(OutT) == 2) {
                *(__half2*)&C[(size_t)rg * 512 + cg] =
                    __floats2half2_rn(acc[m][j].x + bv.x, acc[m][j].y + bv.y);
                *(__half2*)&C[(size_t)(rg + 8) * 512 + cg] =
                    __floats2half2_rn(acc[m][j].z + bv.x, acc[m][j].w + bv.y);
            } else {
                *(float2*)&C[(size_t)rg * 512 + cg] =
                    make_float2(acc[m][j].x + bv.x, acc[m][j].y + bv.y);
                *(float2*)&C[(size_t)(rg + 8) * 512 + cg] =
                    make_float2(acc[m][j].z + bv.x, acc[m][j].w + bv.y);
            }
        }
}

// ---------------------------------------------------------------------------
// proj3: all three projection GEMMs in one launch (z selects Q/K/V).
// ---------------------------------------------------------------------------
__global__ __launch_bounds__(256, 2)
void proj3(const float* __restrict__ bq, const float* __restrict__ bk,
           const float* __restrict__ bv) {
    if (blockIdx.z == 0)      hgemm_body<__half>(g_qin, g_wq, bq, g_qh);
    else if (blockIdx.z == 1) hgemm_body<__half>(g_kin, g_wk, bk, g_kh);
    else                      hgemm_body<__half>(g_vin, g_wv, bv, g_vh);
}

// ---------------------------------------------------------------------------
// out-projection GEMM (standalone)
// ---------------------------------------------------------------------------
__global__ __launch_bounds__(256, 2)
void out_gemm(const float* __restrict__ bo, float* __restrict__ out) {
    hgemm_body<float>(g_ctxh, g_wo, bo, out);
}

// ---------------------------------------------------------------------------
// rescale: attn[row][:] = fp32(g_eh[row][:]) * g_inv[row].
// 4 rows per block, loads front-batched (MLP=4/thread), streaming hints.
// ---------------------------------------------------------------------------
__global__ __launch_bounds__(256)
void rescale_attn(float* __restrict__ attn) {
    const int row0 = blockIdx.x * 4;
    const int tid = threadIdx.x;
    uint4 u[4];
    float iv[4];
#pragma unroll
    for (int r = 0; r < 4; r++)
        u[r] = __ldcs(&reinterpret_cast<const uint4*>(g_eh + (size_t)(row0 + r) * L_)[tid]);
#pragma unroll
    for (int r = 0; r < 4; r++) iv[r] = g_inv[row0 + r];
#pragma unroll
    for (int r = 0; r < 4; r++) {
        const float2 f0 = __half22float2(*(const __half2*)&u[r].x);
        const float2 f1 = __half22float2(*(const __half2*)&u[r].y);
        const float2 f2 = __half22float2(*(const __half2*)&u[r].z);
        const float2 f3 = __half22float2(*(const __half2*)&u[r].w);
        float4* d = reinterpret_cast<float4*>(attn + (size_t)(row0 + r) * L_);
        __stcs(&d[2 * tid],     make_float4(f0.x * iv[r], f0.y * iv[r], f1.x * iv[r], f1.y * iv[r]));
        __stcs(&d[2 * tid + 1], make_float4(f2.x * iv[r], f2.y * iv[r], f3.x * iv[r], f3.y * iv[r]));
    }
}

// ---------------------------------------------------------------------------
// fp16 fused attention (bitmask, mask prefetch, store-early, coalesced ctx).
// CTA = (bh, 128 q rows); warp owns 16 q-rows x 64 kv.
// ---------------------------------------------------------------------------
__global__ __launch_bounds__(256, 2)
void attn_fp16(float* __restrict__ dummy) {
    extern __shared__ __half smh[];
    __half* qs = smh;                  // [128][72]
    __half* ks = qs + 128 * 72;        // [2][64][72]
    __half* vs = ks + 2 * 64 * 72;     // [2][64][72]
    __half* es = vs + 2 * 64 * 72;     // [128][72] (64 cols used)
    float* red = (float*)(es + 128 * 72);   // [128]

    const int tid = threadIdx.x, l = tid & 31, w = tid >> 5;
    const int wq = w * 16;
    const int g = l >> 2, tig = l & 3;
    const int qt = blockIdx.x, bh = blockIdx.y, b = bh >> 3;
    const int q0 = qt * 128;

    const __half* qg = g_qh + ((size_t)bh * L_ + q0) * DH_;
    const __half* kg = g_kh + (size_t)bh * L_ * DH_;
    const __half* vg = g_vh + (size_t)bh * L_ * DH_;
    const uint8_t* mbB = (const uint8_t*)g_maskb + ((size_t)b * L_ * L_ >> 3);

    const uint32_t qs_s = (uint32_t)__cvta_generic_to_shared(qs);
    const uint32_t ks_s = (uint32_t)__cvta_generic_to_shared(ks);
    const uint32_t vs_s = (uint32_t)__cvta_generic_to_shared(vs);

#define ISSUE_K(kt_, buf_)                                                     \
    do {                                                                       \
        _Pragma("unroll")                                                      \
        for (int t = 0; t < 2; t++) {                                          \
            const int s = tid + 256 * t;                                       \
            const int r = s >> 3, c = (s & 7) << 3;                            \
            cpa16(ks_s + (uint32_t)(((buf_) * 64 * 72 + r * 72 + c) * 2),      \
                  kg + (size_t)((kt_) * 64 + r) * DH_ + c);                    \
        }                                                                      \
        cpcommit();                                                            \
    } while (0)
#define ISSUE_V(kt_, buf_)                                                     \
    do {                                                                       \
        _Pragma("unroll")                                                      \
        for (int t = 0; t < 2; t++) {                                          \
            const int s = tid + 256 * t;                                       \
            const int r = s >> 3, c = (s & 7) << 3;                            \
            cpa16(vs_s + (uint32_t)(((buf_) * 64 * 72 + r * 72 + c) * 2),      \
                  vg + (size_t)((kt_) * 64 + r) * DH_ + c);                    \
        }                                                                      \
        cpcommit();                                                            \
    } while (0)

    // Q (group), K0 (group), V0 (group)
#pragma unroll
    for (int t = 0; t < 4; t++) {
        const int s = tid + 256 * t;
        const int r = s >> 3, c = (s & 7) << 3;
        cpa16(qs_s + (uint32_t)((r * 72 + c) * 2), qg + (size_t)r * DH_ + c);
    }
    cpcommit();
    ISSUE_K(0, 0);
    ISSUE_V(0, 0);

    // ldmatrix lane addressing
    const int a_row = wq + (l & 15);
    const int a_col = (l >> 4) << 3;
    const int kb_row = ((l >> 4) << 3) + (l & 7);
    const int kb_col = ((l >> 3) & 1) << 3;
    const int vb_row = (((l >> 3) & 1) << 3) + (l & 7);
    const int vb_col = (l >> 4) << 3;

    cpwait<2>();
    __syncthreads();

    uint32_t qa[4][4];
    const uint32_t qaddr = qs_s + (uint32_t)((a_row * 72 + a_col) * 2);
#pragma unroll
    for (int kc = 0; kc < 4; kc++)
        ldsm4(qa[kc][0], qa[kc][1], qa[kc][2], qa[kc][3], qaddr + kc * 32);

    float4 ctx[8];
#pragma unroll
    for (int j = 0; j < 8; j++) ctx[j] = make_float4(0.f, 0.f, 0.f, 0.f);
    float rs0 = 0.f, rs1 = 0.f;

    const int rg0 = q0 + wq + g;
    const int rg1 = rg0 + 8;
    const int er0 = wq + g;            // local e rows
    __half* eg = g_eh + ((size_t)bh * L_ + q0) * L_;

    // mask prefetch for kt = 0
    uint64_t m0w = (*(const uint64_t*)(mbB + (size_t)rg0 * 256)) >> (2 * tig);
    uint64_t m1w = (*(const uint64_t*)(mbB + (size_t)rg1 * 256)) >> (2 * tig);

    for (int kt = 0; kt < 32; kt++) {
        const int buf = kt & 1;

        // prefetch next iteration's mask words (issue before the wait/stall)
        uint64_t n0w = 0, n1w = 0;
        if (kt + 1 < 32) {
            n0w = (*(const uint64_t*)(mbB + (size_t)rg0 * 256 + (kt + 1) * 8)) >> (2 * tig);
            n1w = (*(const uint64_t*)(mbB + (size_t)rg1 * 256 + (kt + 1) * 8)) >> (2 * tig);
        }

        cpwait<1>();
        __syncthreads();

        // ---- QK^T ----
        float4 acc[8];
#pragma unroll
        for (int j = 0; j < 8; j++) acc[j] = make_float4(0.f, 0.f, 0.f, 0.f);

        const uint32_t ksb = ks_s + (uint32_t)(buf * 64 * 72 * 2);
#pragma unroll
        for (int kc = 0; kc < 4; kc++) {
#pragma unroll
            for (int q4 = 0; q4 < 4; q4++) {
                uint32_t b0, b1, b2, b3;
                ldsm4(b0, b1, b2, b3,
                      ksb + (uint32_t)(((q4 * 16 + kb_row) * 72 + kc * 16 + kb_col) * 2));
                mma_f16(acc[2 * q4],     qa[kc][0], qa[kc][1], qa[kc][2], qa[kc][3], b0, b1);
                mma_f16(acc[2 * q4 + 1], qa[kc][0], qa[kc][1], qa[kc][2], qa[kc][3], b2, b3);
            }
        }

        if (kt + 1 < 32) ISSUE_K(kt + 1, buf ^ 1);

        // ---- epilogue: bitmask exp -> es smem + register repack ----
        uint32_t plo[8], phi[8];
#pragma unroll
        for (int j = 0; j < 8; j++) {
            const unsigned t0 = (unsigned)(m0w >> (8 * j)) & 3u;
            const unsigned t1 = (unsigned)(m1w >> (8 * j)) & 3u;
            const float e0 = (t0 & 1u) ? exp2f(acc[j].x * LOG2E_DIV32) : 0.f;
            const float e1 = (t0 & 2u) ? exp2f(acc[j].y * LOG2E_DIV32) : 0.f;
            const float e2 = (t1 & 1u) ? exp2f(acc[j].z * LOG2E_DIV32) : 0.f;
            const float e3 = (t1 & 2u) ? exp2f(acc[j].w * LOG2E_DIV32) : 0.f;
            rs0 += e0 + e1;
            rs1 += e2 + e3;
            const __half2 h0 = __floats2half2_rn(e0, e1);
            const __half2 h1 = __floats2half2_rn(e2, e3);
            plo[j] = *(const uint32_t*)&h0;
            phi[j] = *(const uint32_t*)&h1;
            const int cl = 8 * j + 2 * tig;
            *(__half2*)&es[er0 * 72 + cl] = h0;
            *(__half2*)&es[(er0 + 8) * 72 + cl] = h1;
        }
        m0w = n0w;
        m1w = n1w;

        if (kt + 1 < 32) cpwait<1>(); else cpwait<0>();
        __syncthreads();   // publishes es + vs

        // ---- coalesced e tile store FIRST (drains under PV MMAs) ----
#pragma unroll
        for (int t = 0; t < 4; t++) {
            const int s = tid + 256 * t;
            const int r = s >> 3, c = (s & 7) << 3;
            __stcs((uint4*)(eg + (size_t)r * L_ + kt * 64 + c), *(const uint4*)&es[r * 72 + c]);
        }

        // ---- P @ V (A from registers) ----
        const uint32_t vsb = vs_s + (uint32_t)(buf * 64 * 72 * 2);
#pragma unroll
        for (int kc = 0; kc < 4; kc++) {
            const uint32_t a0 = plo[2 * kc], a1 = phi[2 * kc];
            const uint32_t a2 = plo[2 * kc + 1], a3 = phi[2 * kc + 1];
#pragma unroll
            for (int q4 = 0; q4 < 4; q4++) {
                uint32_t b0, b1, b2, b3;
                ldsm4t(b0, b1, b2, b3,
                       vsb + (uint32_t)(((kc * 16 + vb_row) * 72 + q4 * 16 + vb_col) * 2));
                mma_f16(ctx[2 * q4],     a0, a1, a2, a3, b0, b1);
                mma_f16(ctx[2 * q4 + 1], a0, a1, a2, a3, b2, b3);
            }
        }

        if (kt + 1 < 32) ISSUE_V(kt + 1, buf ^ 1);
    }

    // ---- rowsum reduce -> inv ----
    rs0 += __shfl_xor_sync(0xffffffffu, rs0, 1);
    rs0 += __shfl_xor_sync(0xffffffffu, rs0, 2);
    rs1 += __shfl_xor_sync(0xffffffffu, rs1, 1);
    rs1 += __shfl_xor_sync(0xffffffffu, rs1, 2);
    if (tig == 0) {
        red[wq + g] = rs0;
        red[wq + 8 + g] = rs1;
    }
    __syncthreads();
    if (tid < 128) {
        const float s = red[tid];
        const float iv = (s > 0.f) ? (1.f / s) : 0.f;
        g_inv[(size_t)bh * L_ + q0 + tid] = iv;
        red[tid] = iv;
    }
    __syncthreads();
    const float iv0 = red[wq + g];
    const float iv1 = red[wq + 8 + g];

    // ---- ctx: stage normalized fp16 into es, then coalesced store ----
#pragma unroll
    for (int j = 0; j < 8; j++) {
        const int cd = 8 * j + 2 * tig;
        *(__half2*)&es[er0 * 72 + cd] =
            __floats2half2_rn(ctx[j].x * iv0, ctx[j].y * iv0);
        *(__half2*)&es[(er0 + 8) * 72 + cd] =
            __floats2half2_rn(ctx[j].z * iv1, ctx[j].w * iv1);
    }
    __syncthreads();
    // 128 rows x 64 halves tile is contiguous in g_ctxh -> linear uint4 copy
    __half* cg = g_ctxh + ((size_t)bh * L_ + q0) * DH_;
#pragma unroll
    for (int t = 0; t < 4; t++) {
        const int s = tid + 256 * t;
        const int r = s >> 3, c = (s & 7) << 3;
        *(uint4*)(cg + (size_t)r * DH_ + c) = *(const uint4*)&es[r * 72 + c];
    }
    (void)dummy;
#undef ISSUE_K
#undef ISSUE_V
}

// ---------------------------------------------------------------------------
extern "C" void kernel_launch(void* const* d_in, const int* in_sizes, int n_in,
                              void* d_out, int out_size) {
    const float* Q  = (const float*)d_in[0];
    const float* K  = (const float*)d_in[1];
    const float* V  = (const float*)d_in[2];
    const int*   Mk = (const int*)d_in[3];
    const float* Wq = (const float*)d_in[4];
    const float* bq = (const float*)d_in[5];
    const float* Wk = (const float*)d_in[6];
    const float* bk = (const float*)d_in[7];
    const float* Wv = (const float*)d_in[8];
    const float* bv = (const float*)d_in[9];
    const float* Wo = (const float*)d_in[10];
    const float* bo = (const float*)d_in[11];

    float* out  = (float*)d_out;
    float* attn = out + OUT_ELEMS;   // concat(out, attn_dist)

    const int smem_gemm = (2 * 128 * 72 + 2 * 64 * 72) * 2;                  // 55296
    const int smem_attn = (128 * 72 + 4 * 64 * 72 + 128 * 72) * 2 + 128 * 4; // 74240
    cudaFuncSetAttribute(proj3, cudaFuncAttributeMaxDynamicSharedMemorySize, smem_gemm);
    cudaFuncSetAttribute(out_gemm, cudaFuncAttributeMaxDynamicSharedMemorySize, smem_gemm);
    cudaFuncSetAttribute(attn_fp16, cudaFuncAttributeMaxDynamicSharedMemorySize, smem_attn);

    prep<<<2048 + 3 * 4096 + 4 * 256, 256>>>(Mk, Q, K, V, Wq, Wk, Wv, Wo);

    proj3<<<dim3(8, 64, 3), 256, smem_gemm>>>(bq, bk, bv);

    const dim3 ga(16, 32);   // q-tiles of 128, b*h
    attn_fp16<<<ga, 256, smem_attn>>>(attn);

    rescale_attn<<<B_ * H_ * L_ / 4, 256>>>(attn);

    out_gemm<<<dim3(8, 64), 256, smem_gemm>>>(bo, out);
}

// round 14
// speedup vs baseline: 1.0377x; 1.0377x over previous
#include <cuda_runtime.h>
#include <cuda_fp16.h>
#include <cstdint>

#define B_ 4
#define L_ 2048
#define D_ 512
#define H_ 8
#define DH_ 64
#define OUT_ELEMS (B_ * L_ * D_)          // 4194304
#define LOG2E_DIV32 0.04507129744f         // log2(e)/32

// Scratch (__device__ globals; allocation-free rule)
__device__ __half   g_qin[OUT_ELEMS];               // fp16 inputs
__device__ __half   g_kin[OUT_ELEMS];
__device__ __half   g_vin[OUT_ELEMS];
__device__ __half   g_wq[D_ * D_], g_wk[D_ * D_], g_wv[D_ * D_], g_wo[D_ * D_];
__device__ __half   g_qh[OUT_ELEMS];                // fp16 projections
__device__ __half   g_kh[OUT_ELEMS];
__device__ __half   g_vh[OUT_ELEMS];
__device__ __half   g_ctxh[OUT_ELEMS];              // fp16 attention context
__device__ float    g_inv[B_ * H_ * L_];
__device__ uint32_t g_maskb[(size_t)B_ * L_ * L_ / 32];   // 2 MB bitmask
__device__ __half   g_eh[(size_t)B_ * H_ * L_ * L_];      // 268 MB unnormalized e

// ---------------------------------------------------------------------------
// helpers
// ---------------------------------------------------------------------------
__device__ __forceinline__ void mma_f16(float4& d, uint32_t a0, uint32_t a1,
                                        uint32_t a2, uint32_t a3,
                                        uint32_t b0, uint32_t b1) {
    asm volatile(
        "mma.sync.aligned.m16n8k16.row.col.f32.f16.f16.f32 "
        "{%0,%1,%2,%3}, {%4,%5,%6,%7}, {%8,%9}, {%0,%1,%2,%3};"
        : "+f"(d.x), "+f"(d.y), "+f"(d.z), "+f"(d.w)
        : "r"(a0), "r"(a1), "r"(a2), "r"(a3), "r"(b0), "r"(b1));
}
__device__ __forceinline__ void ldsm4(uint32_t& r0, uint32_t& r1, uint32_t& r2,
                                      uint32_t& r3, uint32_t addr) {
    asm volatile("ldmatrix.sync.aligned.m8n8.x4.shared.b16 {%0,%1,%2,%3}, [%4];"
                 : "=r"(r0), "=r"(r1), "=r"(r2), "=r"(r3) : "r"(addr));
}
__device__ __forceinline__ void ldsm4t(uint32_t& r0, uint32_t& r1, uint32_t& r2,
                                       uint32_t& r3, uint32_t addr) {
    asm volatile("ldmatrix.sync.aligned.m8n8.x4.trans.shared.b16 {%0,%1,%2,%3}, [%4];"
                 : "=r"(r0), "=r"(r1), "=r"(r2), "=r"(r3) : "r"(addr));
}
__device__ __forceinline__ void cpa16(uint32_t s, const void* g) {
    asm volatile("cp.async.cg.shared.global [%0], [%1], 16;" :: "r"(s), "l"(g));
}
__device__ __forceinline__ void cpcommit() {
    asm volatile("cp.async.commit_group;" ::: "memory");
}
template <int N> __device__ __forceinline__ void cpwait() {
    asm volatile("cp.async.wait_group %0;" :: "n"(N) : "memory");
}

// ---------------------------------------------------------------------------
// prep: mask -> bitmask (warp ballot) + all fp32->fp16 converts.
// Segments: [0,2048) bitpack | [2048,14336) Q,K,V | [14336,15360) weights
// ---------------------------------------------------------------------------
__global__ __launch_bounds__(256)
void prep(const int* __restrict__ m,
          const float* __restrict__ Q, const float* __restrict__ K,
          const float* __restrict__ V, const float* __restrict__ Wq,
          const float* __restrict__ Wk, const float* __restrict__ Wv,
          const float* __restrict__ Wo) {
    int bx = blockIdx.x;
    if (bx < 2048) {
        // each warp packs 1024 ints -> 32 uint32 words
        const int wg = bx * 8 + (threadIdx.x >> 5);
        const int lane = threadIdx.x & 31;
        const size_t base = (size_t)wg * 1024;
        uint32_t word = 0;
#pragma unroll
        for (int r = 0; r < 32; r++) {
            const int v = m[base + (size_t)r * 32 + lane];
            const unsigned bits = __ballot_sync(0xffffffffu, v != 0);
            if (lane == r) word = bits;
        }
        g_maskb[base / 32 + lane] = word;
        return;
    }
    bx -= 2048;
    const float* s;
    __half* d;
    size_t i;
    if (bx < 3 * 4096) {
        const int seg = bx >> 12;
        const int b2 = bx & 4095;
        s = (seg == 0) ? Q : (seg == 1) ? K : V;
        d = (seg == 0) ? g_qin : (seg == 1) ? g_kin : g_vin;
        i = (size_t)b2 * 256 + threadIdx.x;
    } else {
        bx -= 3 * 4096;
        const int seg = bx >> 8;
        const int b2 = bx & 255;
        s = (seg == 0) ? Wq : (seg == 1) ? Wk : (seg == 2) ? Wv : Wo;
        d = (seg == 0) ? g_wq : (seg == 1) ? g_wk : (seg == 2) ? g_wv : g_wo;
        i = (size_t)b2 * 256 + threadIdx.x;
    }
    const float4 v = reinterpret_cast<const float4*>(s)[i];
    __half2 h0 = __floats2half2_rn(v.x, v.y);
    __half2 h1 = __floats2half2_rn(v.z, v.w);
    uint2 o;
    o.x = *(uint32_t*)&h0;
    o.y = *(uint32_t*)&h1;
    reinterpret_cast<uint2*>(d)[i] = o;
}

// ---------------------------------------------------------------------------
// fp16 GEMM body: C[M,512] = A[M,512] @ W[512,512] + bias (fp32 accum/bias).
// Block 128x64, 8 warps, warp 32x32, k-stage 64, 3-stage cp.async ring.
// smem halves: Ah[3][128][72] + Wh[3][64][72] = 82944 B
// ---------------------------------------------------------------------------
__device__ __forceinline__ void hgemm_issue(const __half* A, const __half* W,
                                            int m0, int n0, uint32_t as_s,
                                            uint32_t bs_s, int ki, int buf,
                                            int tid) {
    const __half* Ap = A + (size_t)m0 * 512 + ki * 64;
#pragma unroll
    for (int t = 0; t < 4; t++) {
        const int s = tid + 256 * t;
        const int r = s >> 3, c = (s & 7) << 3;
        cpa16(as_s + (uint32_t)((buf * 128 * 72 + r * 72 + c) * 2),
              Ap + (size_t)r * 512 + c);
    }
    const __half* Wp = W + (size_t)ki * 64 * 512 + n0;
#pragma unroll
    for (int t = 0; t < 2; t++) {
        const int s = tid + 256 * t;
        const int r = s >> 3, c = (s & 7) << 3;
        cpa16(bs_s + (uint32_t)((buf * 64 * 72 + r * 72 + c) * 2),
              Wp + (size_t)r * 512 + c);
    }
    cpcommit();
}

template <typename OutT>
__device__ __forceinline__ void hgemm_body(const __half* __restrict__ A,
                                           const __half* __restrict__ W,
                                           const float* __restrict__ bias,
                                           OutT* __restrict__ C) {
    extern __shared__ __half smh[];
    __half* Ah = smh;                  // [3][128][72]
    __half* Wh = smh + 3 * 128 * 72;   // [3][64][72]

    const int tid = threadIdx.x, l = tid & 31, w = tid >> 5;
    const int mg = w >> 1, ng = w & 1;
    const int wm = mg * 32, wn = ng * 32;
    const int lr = l >> 2, lc = l & 3;
    const int m0 = blockIdx.y << 7, n0 = blockIdx.x << 6;

    const uint32_t as_s = (uint32_t)__cvta_generic_to_shared(Ah);
    const uint32_t bs_s = (uint32_t)__cvta_generic_to_shared(Wh);

    const int a_row = (l & 15), a_col = (l >> 4) << 3;
    const int vb_row = (((l >> 3) & 1) << 3) + (l & 7);
    const int vb_col = (l >> 4) << 3;

    float4 acc[2][4];
#pragma unroll
    for (int m = 0; m < 2; m++)
#pragma unroll
        for (int j = 0; j < 4; j++) acc[m][j] = make_float4(0.f, 0.f, 0.f, 0.f);

    hgemm_issue(A, W, m0, n0, as_s, bs_s, 0, 0, tid);
    hgemm_issue(A, W, m0, n0, as_s, bs_s, 1, 1, tid);

    for (int ki = 0; ki < 8; ki++) {
        if (ki + 2 < 8) {
            hgemm_issue(A, W, m0, n0, as_s, bs_s, ki + 2, (ki + 2) % 3, tid);
            cpwait<2>();
        } else if (ki == 6) {
            cpwait<1>();
        } else {
            cpwait<0>();
        }
        __syncthreads();

        const int buf = ki % 3;
        const uint32_t a0b = as_s + (uint32_t)((buf * 128 * 72 + (wm + a_row) * 72 + a_col) * 2);
        const uint32_t a1b = a0b + 16 * 72 * 2;
        const uint32_t wb = bs_s + (uint32_t)((buf * 64 * 72) * 2);

#pragma unroll
        for (int kc = 0; kc < 4; kc++) {
            uint32_t a0[4], a1[4];
            ldsm4(a0[0], a0[1], a0[2], a0[3], a0b + kc * 32);
            ldsm4(a1[0], a1[1], a1[2], a1[3], a1b + kc * 32);
#pragma unroll
            for (int j = 0; j < 2; j++) {
                uint32_t b0, b1, b2, b3;
                ldsm4t(b0, b1, b2, b3,
                       wb + (uint32_t)(((kc * 16 + vb_row) * 72 + wn + 16 * j + vb_col) * 2));
                mma_f16(acc[0][2 * j],     a0[0], a0[1], a0[2], a0[3], b0, b1);
                mma_f16(acc[1][2 * j],     a1[0], a1[1], a1[2], a1[3], b0, b1);
                mma_f16(acc[0][2 * j + 1], a0[0], a0[1], a0[2], a0[3], b2, b3);
                mma_f16(acc[1][2 * j + 1], a1[0], a1[1], a1[2], a1[3], b2, b3);
            }
        }
        __syncthreads();
    }

#pragma unroll
    for (int m = 0; m < 2; m++)
#pragma unroll
        for (int j = 0; j < 4; j++) {
            const int rg = m0 + wm + 16 * m + lr;
            const int cg = n0 + wn + 8 * j + 2 * lc;
            const float2 bv = *(const float2*)&bias[cg];
            if constexpr (sizeof(OutT) == 2) {
                *(__half2*)&C[(size_t)rg * 512 + cg] =
                    __floats2half2_rn(acc[m][j].x + bv.x, acc[m][j].y + bv.y);
                *(__half2*)&C[(size_t)(rg + 8) * 512 + cg] =
                    __floats2half2_rn(acc[m][j].z + bv.x, acc[m][j].w + bv.y);
            } else {
                *(float2*)&C[(size_t)rg * 512 + cg] =
                    make_float2(acc[m][j].x + bv.x, acc[m][j].y + bv.y);
                *(float2*)&C[(size_t)(rg + 8) * 512 + cg] =
                    make_float2(acc[m][j].z + bv.x, acc[m][j].w + bv.y);
            }
        }
}

// ---------------------------------------------------------------------------
// proj3: all three projection GEMMs in one launch (z selects Q/K/V).
// ---------------------------------------------------------------------------
__global__ __launch_bounds__(256, 2)
void proj3(const float* __restrict__ bq, const float* __restrict__ bk,
           const float* __restrict__ bv) {
    if (blockIdx.z == 0)      hgemm_body<__half>(g_qin, g_wq, bq, g_qh);
    else if (blockIdx.z == 1) hgemm_body<__half>(g_kin, g_wk, bk, g_kh);
    else                      hgemm_body<__half>(g_vin, g_wv, bv, g_vh);
}

// ---------------------------------------------------------------------------
// out-projection GEMM (standalone)
// ---------------------------------------------------------------------------
__global__ __launch_bounds__(256, 2)
void out_gemm(const float* __restrict__ bo, float* __restrict__ out) {
    hgemm_body<float>(g_ctxh, g_wo, bo, out);
}

// ---------------------------------------------------------------------------
// rescale: attn[row][:] = fp32(g_eh[row][:]) * g_inv[row].
// 2 rows per block (MLP=2), streaming hints — measured-best shape (R12).
// ---------------------------------------------------------------------------
__global__ __launch_bounds__(256)
void rescale_attn(float* __restrict__ attn) {
    const int row0 = blockIdx.x * 2;
    const int row1 = row0 + 1;
    const float iv0 = g_inv[row0];
    const float iv1 = g_inv[row1];
    const int tid = threadIdx.x;
    const uint4 u0 = __ldcs(&reinterpret_cast<const uint4*>(g_eh + (size_t)row0 * L_)[tid]);
    const uint4 u1 = __ldcs(&reinterpret_cast<const uint4*>(g_eh + (size_t)row1 * L_)[tid]);

    float4* d0 = reinterpret_cast<float4*>(attn + (size_t)row0 * L_);
    float4* d1 = reinterpret_cast<float4*>(attn + (size_t)row1 * L_);
    {
        const float2 f0 = __half22float2(*(const __half2*)&u0.x);
        const float2 f1 = __half22float2(*(const __half2*)&u0.y);
        const float2 f2 = __half22float2(*(const __half2*)&u0.z);
        const float2 f3 = __half22float2(*(const __half2*)&u0.w);
        __stcs(&d0[2 * tid],     make_float4(f0.x * iv0, f0.y * iv0, f1.x * iv0, f1.y * iv0));
        __stcs(&d0[2 * tid + 1], make_float4(f2.x * iv0, f2.y * iv0, f3.x * iv0, f3.y * iv0));
    }
    {
        const float2 f0 = __half22float2(*(const __half2*)&u1.x);
        const float2 f1 = __half22float2(*(const __half2*)&u1.y);
        const float2 f2 = __half22float2(*(const __half2*)&u1.z);
        const float2 f3 = __half22float2(*(const __half2*)&u1.w);
        __stcs(&d1[2 * tid],     make_float4(f0.x * iv1, f0.y * iv1, f1.x * iv1, f1.y * iv1));
        __stcs(&d1[2 * tid + 1], make_float4(f2.x * iv1, f2.y * iv1, f3.x * iv1, f3.y * iv1));
    }
}

// ---------------------------------------------------------------------------
// fp16 fused attention (R12 version: bitmask, mask prefetch, store-early).
// CTA = (bh, 128 q rows); warp owns 16 q-rows x 64 kv.
// ---------------------------------------------------------------------------
__global__ __launch_bounds__(256, 2)
void attn_fp16(float* __restrict__ dummy) {
    extern __shared__ __half smh[];
    __half* qs = smh;                  // [128][72]
    __half* ks = qs + 128 * 72;        // [2][64][72]
    __half* vs = ks + 2 * 64 * 72;     // [2][64][72]
    __half* es = vs + 2 * 64 * 72;     // [128][72] (64 cols used)
    float* red = (float*)(es + 128 * 72);   // [128]

    const int tid = threadIdx.x, l = tid & 31, w = tid >> 5;
    const int wq = w * 16;
    const int g = l >> 2, tig = l & 3;
    const int qt = blockIdx.x, bh = blockIdx.y, b = bh >> 3;
    const int q0 = qt * 128;

    const __half* qg = g_qh + ((size_t)bh * L_ + q0) * DH_;
    const __half* kg = g_kh + (size_t)bh * L_ * DH_;
    const __half* vg = g_vh + (size_t)bh * L_ * DH_;
    const uint8_t* mbB = (const uint8_t*)g_maskb + ((size_t)b * L_ * L_ >> 3);

    const uint32_t qs_s = (uint32_t)__cvta_generic_to_shared(qs);
    const uint32_t ks_s = (uint32_t)__cvta_generic_to_shared(ks);
    const uint32_t vs_s = (uint32_t)__cvta_generic_to_shared(vs);

#define ISSUE_K(kt_, buf_)                                                     \
    do {                                                                       \
        _Pragma("unroll")                                                      \
        for (int t = 0; t < 2; t++) {                                          \
            const int s = tid + 256 * t;                                       \
            const int r = s >> 3, c = (s & 7) << 3;                            \
            cpa16(ks_s + (uint32_t)(((buf_) * 64 * 72 + r * 72 + c) * 2),      \
                  kg + (size_t)((kt_) * 64 + r) * DH_ + c);                    \
        }                                                                      \
        cpcommit();                                                            \
    } while (0)
#define ISSUE_V(kt_, buf_)                                                     \
    do {                                                                       \
        _Pragma("unroll")                                                      \
        for (int t = 0; t < 2; t++) {                                          \
            const int s = tid + 256 * t;                                       \
            const int r = s >> 3, c = (s & 7) << 3;                            \
            cpa16(vs_s + (uint32_t)(((buf_) * 64 * 72 + r * 72 + c) * 2),      \
                  vg + (size_t)((kt_) * 64 + r) * DH_ + c);                    \
        }                                                                      \
        cpcommit();                                                            \
    } while (0)

    // Q (group), K0 (group), V0 (group)
#pragma unroll
    for (int t = 0; t < 4; t++) {
        const int s = tid + 256 * t;
        const int r = s >> 3, c = (s & 7) << 3;
        cpa16(qs_s + (uint32_t)((r * 72 + c) * 2), qg + (size_t)r * DH_ + c);
    }
    cpcommit();
    ISSUE_K(0, 0);
    ISSUE_V(0, 0);

    // ldmatrix lane addressing
    const int a_row = wq + (l & 15);
    const int a_col = (l >> 4) << 3;
    const int kb_row = ((l >> 4) << 3) + (l & 7);
    const int kb_col = ((l >> 3) & 1) << 3;
    const int vb_row = (((l >> 3) & 1) << 3) + (l & 7);
    const int vb_col = (l >> 4) << 3;

    cpwait<2>();
    __syncthreads();

    uint32_t qa[4][4];
    const uint32_t qaddr = qs_s + (uint32_t)((a_row * 72 + a_col) * 2);
#pragma unroll
    for (int kc = 0; kc < 4; kc++)
        ldsm4(qa[kc][0], qa[kc][1], qa[kc][2], qa[kc][3], qaddr + kc * 32);

    float4 ctx[8];
#pragma unroll
    for (int j = 0; j < 8; j++) ctx[j] = make_float4(0.f, 0.f, 0.f, 0.f);
    float rs0 = 0.f, rs1 = 0.f;

    const int rg0 = q0 + wq + g;
    const int rg1 = rg0 + 8;
    const int er0 = wq + g;            // local e rows
    __half* eg = g_eh + ((size_t)bh * L_ + q0) * L_;

    // mask prefetch for kt = 0
    uint64_t m0w = (*(const uint64_t*)(mbB + (size_t)rg0 * 256)) >> (2 * tig);
    uint64_t m1w = (*(const uint64_t*)(mbB + (size_t)rg1 * 256)) >> (2 * tig);

    for (int kt = 0; kt < 32; kt++) {
        const int buf = kt & 1;
        cpwait<1>();
        __syncthreads();

        // prefetch next iteration's mask words (resolve under QK MMAs)
        uint64_t n0w = 0, n1w = 0;
        if (kt + 1 < 32) {
            n0w = (*(const uint64_t*)(mbB + (size_t)rg0 * 256 + (kt + 1) * 8)) >> (2 * tig);
            n1w = (*(const uint64_t*)(mbB + (size_t)rg1 * 256 + (kt + 1) * 8)) >> (2 * tig);
        }

        // ---- QK^T ----
        float4 acc[8];
#pragma unroll
        for (int j = 0; j < 8; j++) acc[j] = make_float4(0.f, 0.f, 0.f, 0.f);

        const uint32_t ksb = ks_s + (uint32_t)(buf * 64 * 72 * 2);
#pragma unroll
        for (int kc = 0; kc < 4; kc++) {
#pragma unroll
            for (int q4 = 0; q4 < 4; q4++) {
                uint32_t b0, b1, b2, b3;
                ldsm4(b0, b1, b2, b3,
                      ksb + (uint32_t)(((q4 * 16 + kb_row) * 72 + kc * 16 + kb_col) * 2));
                mma_f16(acc[2 * q4],     qa[kc][0], qa[kc][1], qa[kc][2], qa[kc][3], b0, b1);
                mma_f16(acc[2 * q4 + 1], qa[kc][0], qa[kc][1], qa[kc][2], qa[kc][3], b2, b3);
            }
        }

        if (kt + 1 < 32) ISSUE_K(kt + 1, buf ^ 1);

        // ---- epilogue: bitmask exp -> es smem + register repack ----
        uint32_t plo[8], phi[8];
#pragma unroll
        for (int j = 0; j < 8; j++) {
            const unsigned t0 = (unsigned)(m0w >> (8 * j)) & 3u;
            const unsigned t1 = (unsigned)(m1w >> (8 * j)) & 3u;
            const float e0 = (t0 & 1u) ? exp2f(acc[j].x * LOG2E_DIV32) : 0.f;
            const float e1 = (t0 & 2u) ? exp2f(acc[j].y * LOG2E_DIV32) : 0.f;
            const float e2 = (t1 & 1u) ? exp2f(acc[j].z * LOG2E_DIV32) : 0.f;
            const float e3 = (t1 & 2u) ? exp2f(acc[j].w * LOG2E_DIV32) : 0.f;
            rs0 += e0 + e1;
            rs1 += e2 + e3;
            const __half2 h0 = __floats2half2_rn(e0, e1);
            const __half2 h1 = __floats2half2_rn(e2, e3);
            plo[j] = *(const uint32_t*)&h0;
            phi[j] = *(const uint32_t*)&h1;
            const int cl = 8 * j + 2 * tig;
            *(__half2*)&es[er0 * 72 + cl] = h0;
            *(__half2*)&es[(er0 + 8) * 72 + cl] = h1;
        }
        m0w = n0w;
        m1w = n1w;

        if (kt + 1 < 32) cpwait<1>(); else cpwait<0>();
        __syncthreads();   // publishes es + vs

        // ---- coalesced e tile store FIRST (drains under PV MMAs) ----
#pragma unroll
        for (int t = 0; t < 4; t++) {
            const int s = tid + 256 * t;
            const int r = s >> 3, c = (s & 7) << 3;
            __stcs((uint4*)(eg + (size_t)r * L_ + kt * 64 + c), *(const uint4*)&es[r * 72 + c]);
        }

        // ---- P @ V (A from registers) ----
        const uint32_t vsb = vs_s + (uint32_t)(buf * 64 * 72 * 2);
#pragma unroll
        for (int kc = 0; kc < 4; kc++) {
            const uint32_t a0 = plo[2 * kc], a1 = phi[2 * kc];
            const uint32_t a2 = plo[2 * kc + 1], a3 = phi[2 * kc + 1];
#pragma unroll
            for (int q4 = 0; q4 < 4; q4++) {
                uint32_t b0, b1, b2, b3;
                ldsm4t(b0, b1, b2, b3,
                       vsb + (uint32_t)(((kc * 16 + vb_row) * 72 + q4 * 16 + vb_col) * 2));
                mma_f16(ctx[2 * q4],     a0, a1, a2, a3, b0, b1);
                mma_f16(ctx[2 * q4 + 1], a0, a1, a2, a3, b2, b3);
            }
        }

        if (kt + 1 < 32) ISSUE_V(kt + 1, buf ^ 1);
    }

    // ---- rowsum reduce -> inv ----
    rs0 += __shfl_xor_sync(0xffffffffu, rs0, 1);
    rs0 += __shfl_xor_sync(0xffffffffu, rs0, 2);
    rs1 += __shfl_xor_sync(0xffffffffu, rs1, 1);
    rs1 += __shfl_xor_sync(0xffffffffu, rs1, 2);
    if (tig == 0) {
        red[wq + g] = rs0;
        red[wq + 8 + g] = rs1;
    }
    __syncthreads();
    if (tid < 128) {
        const float s = red[tid];
        const float iv = (s > 0.f) ? (1.f / s) : 0.f;
        g_inv[(size_t)bh * L_ + q0 + tid] = iv;
        red[tid] = iv;
    }
    __syncthreads();
    const float iv0 = red[wq + g];
    const float iv1 = red[wq + 8 + g];

    // ---- ctx write (normalized fp16) ----
#pragma unroll
    for (int j = 0; j < 8; j++) {
        const int cd = 8 * j + 2 * tig;
        *(__half2*)&g_ctxh[((size_t)bh * L_ + rg0) * DH_ + cd] =
            __floats2half2_rn(ctx[j].x * iv0, ctx[j].y * iv0);
        *(__half2*)&g_ctxh[((size_t)bh * L_ + rg1) * DH_ + cd] =
            __floats2half2_rn(ctx[j].z * iv1, ctx[j].w * iv1);
    }
    (void)dummy;
#undef ISSUE_K
#undef ISSUE_V
}

// ---------------------------------------------------------------------------
extern "C" void kernel_launch(void* const* d_in, const int* in_sizes, int n_in,
                              void* d_out, int out_size) {
    const float* Q  = (const float*)d_in[0];
    const float* K  = (const float*)d_in[1];
    const float* V  = (const float*)d_in[2];
    const int*   Mk = (const int*)d_in[3];
    const float* Wq = (const float*)d_in[4];
    const float* bq = (const float*)d_in[5];
    const float* Wk = (const float*)d_in[6];
    const float* bk = (const float*)d_in[7];
    const float* Wv = (const float*)d_in[8];
    const float* bv = (const float*)d_in[9];
    const float* Wo = (const float*)d_in[10];
    const float* bo = (const float*)d_in[11];

    float* out  = (float*)d_out;
    float* attn = out + OUT_ELEMS;   // concat(out, attn_dist)

    const int smem_gemm = (3 * 128 * 72 + 3 * 64 * 72) * 2;                  // 82944
    const int smem_attn = (128 * 72 + 4 * 64 * 72 + 128 * 72) * 2 + 128 * 4; // 74240
    cudaFuncSetAttribute(proj3, cudaFuncAttributeMaxDynamicSharedMemorySize, smem_gemm);
    cudaFuncSetAttribute(out_gemm, cudaFuncAttributeMaxDynamicSharedMemorySize, smem_gemm);
    cudaFuncSetAttribute(attn_fp16, cudaFuncAttributeMaxDynamicSharedMemorySize, smem_attn);

    prep<<<2048 + 3 * 4096 + 4 * 256, 256>>>(Mk, Q, K, V, Wq, Wk, Wv, Wo);

    proj3<<<dim3(8, 64, 3), 256, smem_gemm>>>(bq, bk, bv);

    const dim3 ga(16, 32);   // q-tiles of 128, b*h
    attn_fp16<<<ga, 256, smem_attn>>>(attn);

    rescale_attn<<<B_ * H_ * L_ / 2, 256>>>(attn);

    out_gemm<<<dim3(8, 64), 256, smem_gemm>>>(bo, out);
}

// round 15
// speedup vs baseline: 1.0420x; 1.0041x over previous
#include <cuda_runtime.h>
#include <cuda_fp16.h>
#include <cstdint>

#define B_ 4
#define L_ 2048
#define D_ 512
#define H_ 8
#define DH_ 64
#define OUT_ELEMS (B_ * L_ * D_)          // 4194304
#define LOG2E_DIV32 0.04507129744f         // log2(e)/32

// Scratch (__device__ globals; allocation-free rule)
__device__ __half   g_qin[OUT_ELEMS];               // fp16 inputs
__device__ __half   g_kin[OUT_ELEMS];
__device__ __half   g_vin[OUT_ELEMS];
__device__ __half   g_wq[D_ * D_], g_wk[D_ * D_], g_wv[D_ * D_], g_wo[D_ * D_];
__device__ __half   g_qh[OUT_ELEMS];                // fp16 projections
__device__ __half   g_kh[OUT_ELEMS];
__device__ __half   g_vh[OUT_ELEMS];
__device__ __half   g_ctxh[OUT_ELEMS];              // fp16 attention context
__device__ float    g_inv[B_ * H_ * L_];
__device__ uint32_t g_maskb[(size_t)B_ * L_ * L_ / 32];   // 2 MB bitmask
__device__ __half   g_eh[(size_t)B_ * H_ * L_ * L_];      // 268 MB unnormalized e

// ---------------------------------------------------------------------------
// helpers
// ---------------------------------------------------------------------------
__device__ __forceinline__ void mma_f16(float4& d, uint32_t a0, uint32_t a1,
                                        uint32_t a2, uint32_t a3,
                                        uint32_t b0, uint32_t b1) {
    asm volatile(
        "mma.sync.aligned.m16n8k16.row.col.f32.f16.f16.f32 "
        "{%0,%1,%2,%3}, {%4,%5,%6,%7}, {%8,%9}, {%0,%1,%2,%3};"
        : "+f"(d.x), "+f"(d.y), "+f"(d.z), "+f"(d.w)
        : "r"(a0), "r"(a1), "r"(a2), "r"(a3), "r"(b0), "r"(b1));
}
__device__ __forceinline__ void ldsm4(uint32_t& r0, uint32_t& r1, uint32_t& r2,
                                      uint32_t& r3, uint32_t addr) {
    asm volatile("ldmatrix.sync.aligned.m8n8.x4.shared.b16 {%0,%1,%2,%3}, [%4];"
                 : "=r"(r0), "=r"(r1), "=r"(r2), "=r"(r3) : "r"(addr));
}
__device__ __forceinline__ void ldsm4t(uint32_t& r0, uint32_t& r1, uint32_t& r2,
                                       uint32_t& r3, uint32_t addr) {
    asm volatile("ldmatrix.sync.aligned.m8n8.x4.trans.shared.b16 {%0,%1,%2,%3}, [%4];"
                 : "=r"(r0), "=r"(r1), "=r"(r2), "=r"(r3) : "r"(addr));
}
__device__ __forceinline__ void cpa16(uint32_t s, const void* g) {
    asm volatile("cp.async.cg.shared.global [%0], [%1], 16;" :: "r"(s), "l"(g));
}
__device__ __forceinline__ void cpcommit() {
    asm volatile("cp.async.commit_group;" ::: "memory");
}
template <int N> __device__ __forceinline__ void cpwait() {
    asm volatile("cp.async.wait_group %0;" :: "n"(N) : "memory");
}

// ---------------------------------------------------------------------------
// pack_mask: mask int32 -> bitmask (warp ballot). 2048 blocks.
// ---------------------------------------------------------------------------
__global__ __launch_bounds__(256)
void pack_mask(const int* __restrict__ m) {
    const int wg = blockIdx.x * 8 + (threadIdx.x >> 5);
    const int lane = threadIdx.x & 31;
    const size_t base = (size_t)wg * 1024;
    uint32_t word = 0;
#pragma unroll
    for (int r = 0; r < 32; r++) {
        const int v = m[base + (size_t)r * 32 + lane];
        const unsigned bits = __ballot_sync(0xffffffffu, v != 0);
        if (lane == r) word = bits;
    }
    g_maskb[base / 32 + lane] = word;
}

// ---------------------------------------------------------------------------
// convert_f2h: Q,K,V + 4 weights fp32->fp16. 13312 blocks.
// Segments: [0,12288) Q,K,V | [12288,13312) weights
// ---------------------------------------------------------------------------
__global__ __launch_bounds__(256)
void convert_f2h(const float* __restrict__ Q, const float* __restrict__ K,
                 const float* __restrict__ V, const float* __restrict__ Wq,
                 const float* __restrict__ Wk, const float* __restrict__ Wv,
                 const float* __restrict__ Wo) {
    int bx = blockIdx.x;
    const float* s;
    __half* d;
    size_t i;
    if (bx < 3 * 4096) {
        const int seg = bx >> 12;
        const int b2 = bx & 4095;
        s = (seg == 0) ? Q : (seg == 1) ? K : V;
        d = (seg == 0) ? g_qin : (seg == 1) ? g_kin : g_vin;
        i = (size_t)b2 * 256 + threadIdx.x;
    } else {
        bx -= 3 * 4096;
        const int seg = bx >> 8;
        const int b2 = bx & 255;
        s = (seg == 0) ? Wq : (seg == 1) ? Wk : (seg == 2) ? Wv : Wo;
        d = (seg == 0) ? g_wq : (seg == 1) ? g_wk : (seg == 2) ? g_wv : g_wo;
        i = (size_t)b2 * 256 + threadIdx.x;
    }
    const float4 v = reinterpret_cast<const float4*>(s)[i];
    __half2 h0 = __floats2half2_rn(v.x, v.y);
    __half2 h1 = __floats2half2_rn(v.z, v.w);
    uint2 o;
    o.x = *(uint32_t*)&h0;
    o.y = *(uint32_t*)&h1;
    reinterpret_cast<uint2*>(d)[i] = o;
}

// ---------------------------------------------------------------------------
// fp16 GEMM body (3-stage cp.async ring). Block 128x64, 8 warps, warp 32x32.
// ---------------------------------------------------------------------------
__device__ __forceinline__ void hgemm_issue(const __half* A, const __half* W,
                                            int m0, int n0, uint32_t as_s,
                                            uint32_t bs_s, int ki, int buf,
                                            int tid) {
    const __half* Ap = A + (size_t)m0 * 512 + ki * 64;
#pragma unroll
    for (int t = 0; t < 4; t++) {
        const int s = tid + 256 * t;
        const int r = s >> 3, c = (s & 7) << 3;
        cpa16(as_s + (uint32_t)((buf * 128 * 72 + r * 72 + c) * 2),
              Ap + (size_t)r * 512 + c);
    }
    const __half* Wp = W + (size_t)ki * 64 * 512 + n0;
#pragma unroll
    for (int t = 0; t < 2; t++) {
        const int s = tid + 256 * t;
        const int r = s >> 3, c = (s & 7) << 3;
        cpa16(bs_s + (uint32_t)((buf * 64 * 72 + r * 72 + c) * 2),
              Wp + (size_t)r * 512 + c);
    }
    cpcommit();
}

template <typename OutT>
__device__ __forceinline__ void hgemm_body(const __half* __restrict__ A,
                                           const __half* __restrict__ W,
                                           const float* __restrict__ bias,
                                           OutT* __restrict__ C) {
    extern __shared__ __half smh[];
    __half* Ah = smh;                  // [3][128][72]
    __half* Wh = smh + 3 * 128 * 72;   // [3][64][72]

    const int tid = threadIdx.x, l = tid & 31, w = tid >> 5;
    const int mg = w >> 1, ng = w & 1;
    const int wm = mg * 32, wn = ng * 32;
    const int lr = l >> 2, lc = l & 3;
    const int m0 = blockIdx.y << 7, n0 = blockIdx.x << 6;

    const uint32_t as_s = (uint32_t)__cvta_generic_to_shared(Ah);
    const uint32_t bs_s = (uint32_t)__cvta_generic_to_shared(Wh);

    const int a_row = (l & 15), a_col = (l >> 4) << 3;
    const int vb_row = (((l >> 3) & 1) << 3) + (l & 7);
    const int vb_col = (l >> 4) << 3;

    float4 acc[2][4];
#pragma unroll
    for (int m = 0; m < 2; m++)
#pragma unroll
        for (int j = 0; j < 4; j++) acc[m][j] = make_float4(0.f, 0.f, 0.f, 0.f);

    hgemm_issue(A, W, m0, n0, as_s, bs_s, 0, 0, tid);
    hgemm_issue(A, W, m0, n0, as_s, bs_s, 1, 1, tid);

    for (int ki = 0; ki < 8; ki++) {
        if (ki + 2 < 8) {
            hgemm_issue(A, W, m0, n0, as_s, bs_s, ki + 2, (ki + 2) % 3, tid);
            cpwait<2>();
        } else if (ki == 6) {
            cpwait<1>();
        } else {
            cpwait<0>();
        }
        __syncthreads();

        const int buf = ki % 3;
        const uint32_t a0b = as_s + (uint32_t)((buf * 128 * 72 + (wm + a_row) * 72 + a_col) * 2);
        const uint32_t a1b = a0b + 16 * 72 * 2;
        const uint32_t wb = bs_s + (uint32_t)((buf * 64 * 72) * 2);

#pragma unroll
        for (int kc = 0; kc < 4; kc++) {
            uint32_t a0[4], a1[4];
            ldsm4(a0[0], a0[1], a0[2], a0[3], a0b + kc * 32);
            ldsm4(a1[0], a1[1], a1[2], a1[3], a1b + kc * 32);
#pragma unroll
            for (int j = 0; j < 2; j++) {
                uint32_t b0, b1, b2, b3;
                ldsm4t(b0, b1, b2, b3,
                       wb + (uint32_t)(((kc * 16 + vb_row) * 72 + wn + 16 * j + vb_col) * 2));
                mma_f16(acc[0][2 * j],     a0[0], a0[1], a0[2], a0[3], b0, b1);
                mma_f16(acc[1][2 * j],     a1[0], a1[1], a1[2], a1[3], b0, b1);
                mma_f16(acc[0][2 * j + 1], a0[0], a0[1], a0[2], a0[3], b2, b3);
                mma_f16(acc[1][2 * j + 1], a1[0], a1[1], a1[2], a1[3], b2, b3);
            }
        }
        __syncthreads();
    }

#pragma unroll
    for (int m = 0; m < 2; m++)
#pragma unroll
        for (int j = 0; j < 4; j++) {
            const int rg = m0 + wm + 16 * m + lr;
            const int cg = n0 + wn + 8 * j + 2 * lc;
            const float2 bv = *(const float2*)&bias[cg];
            if constexpr (sizeof(OutT) == 2) {
                *(__half2*)&C[(size_t)rg * 512 + cg] =
                    __floats2half2_rn(acc[m][j].x + bv.x, acc[m][j].y + bv.y);
                *(__half2*)&C[(size_t)(rg + 8) * 512 + cg] =
                    __floats2half2_rn(acc[m][j].z + bv.x, acc[m][j].w + bv.y);
            } else {
                *(float2*)&C[(size_t)rg * 512 + cg] =
                    make_float2(acc[m][j].x + bv.x, acc[m][j].y + bv.y);
                *(float2*)&C[(size_t)(rg + 8) * 512 + cg] =
                    make_float2(acc[m][j].z + bv.x, acc[m][j].w + bv.y);
            }
        }
}

__global__ __launch_bounds__(256, 2)
void proj3(const float* __restrict__ bq, const float* __restrict__ bk,
           const float* __restrict__ bv) {
    if (blockIdx.z == 0)      hgemm_body<__half>(g_qin, g_wq, bq, g_qh);
    else if (blockIdx.z == 1) hgemm_body<__half>(g_kin, g_wk, bk, g_kh);
    else                      hgemm_body<__half>(g_vin, g_wv, bv, g_vh);
}

__global__ __launch_bounds__(256, 2)
void out_gemm(const float* __restrict__ bo, float* __restrict__ out) {
    hgemm_body<float>(g_ctxh, g_wo, bo, out);
}

// ---------------------------------------------------------------------------
// rescale: attn[row][:] = fp32(g_eh[row][:]) * g_inv[row]. 2 rows/block.
// ---------------------------------------------------------------------------
__global__ __launch_bounds__(256)
void rescale_attn(float* __restrict__ attn) {
    const int row0 = blockIdx.x * 2;
    const int row1 = row0 + 1;
    const float iv0 = g_inv[row0];
    const float iv1 = g_inv[row1];
    const int tid = threadIdx.x;
    const uint4 u0 = __ldcs(&reinterpret_cast<const uint4*>(g_eh + (size_t)row0 * L_)[tid]);
    const uint4 u1 = __ldcs(&reinterpret_cast<const uint4*>(g_eh + (size_t)row1 * L_)[tid]);

    float4* d0 = reinterpret_cast<float4*>(attn + (size_t)row0 * L_);
    float4* d1 = reinterpret_cast<float4*>(attn + (size_t)row1 * L_);
    {
        const float2 f0 = __half22float2(*(const __half2*)&u0.x);
        const float2 f1 = __half22float2(*(const __half2*)&u0.y);
        const float2 f2 = __half22float2(*(const __half2*)&u0.z);
        const float2 f3 = __half22float2(*(const __half2*)&u0.w);
        __stcs(&d0[2 * tid],     make_float4(f0.x * iv0, f0.y * iv0, f1.x * iv0, f1.y * iv0));
        __stcs(&d0[2 * tid + 1], make_float4(f2.x * iv0, f2.y * iv0, f3.x * iv0, f3.y * iv0));
    }
    {
        const float2 f0 = __half22float2(*(const __half2*)&u1.x);
        const float2 f1 = __half22float2(*(const __half2*)&u1.y);
        const float2 f2 = __half22float2(*(const __half2*)&u1.z);
        const float2 f3 = __half22float2(*(const __half2*)&u1.w);
        __stcs(&d1[2 * tid],     make_float4(f0.x * iv1, f0.y * iv1, f1.x * iv1, f1.y * iv1));
        __stcs(&d1[2 * tid + 1], make_float4(f2.x * iv1, f2.y * iv1, f3.x * iv1, f3.y * iv1));
    }
}

// ---------------------------------------------------------------------------
// fp16 fused attention (R12/R14 best version).
// ---------------------------------------------------------------------------
__global__ __launch_bounds__(256, 2)
void attn_fp16(float* __restrict__ dummy) {
    extern __shared__ __half smh[];
    __half* qs = smh;                  // [128][72]
    __half* ks = qs + 128 * 72;        // [2][64][72]
    __half* vs = ks + 2 * 64 * 72;     // [2][64][72]
    __half* es = vs + 2 * 64 * 72;     // [128][72] (64 cols used)
    float* red = (float*)(es + 128 * 72);   // [128]

    const int tid = threadIdx.x, l = tid & 31, w = tid >> 5;
    const int wq = w * 16;
    const int g = l >> 2, tig = l & 3;
    const int qt = blockIdx.x, bh = blockIdx.y, b = bh >> 3;
    const int q0 = qt * 128;

    const __half* qg = g_qh + ((size_t)bh * L_ + q0) * DH_;
    const __half* kg = g_kh + (size_t)bh * L_ * DH_;
    const __half* vg = g_vh + (size_t)bh * L_ * DH_;
    const uint8_t* mbB = (const uint8_t*)g_maskb + ((size_t)b * L_ * L_ >> 3);

    const uint32_t qs_s = (uint32_t)__cvta_generic_to_shared(qs);
    const uint32_t ks_s = (uint32_t)__cvta_generic_to_shared(ks);
    const uint32_t vs_s = (uint32_t)__cvta_generic_to_shared(vs);

#define ISSUE_K(kt_, buf_)                                                     \
    do {                                                                       \
        _Pragma("unroll")                                                      \
        for (int t = 0; t < 2; t++) {                                          \
            const int s = tid + 256 * t;                                       \
            const int r = s >> 3, c = (s & 7) << 3;                            \
            cpa16(ks_s + (uint32_t)(((buf_) * 64 * 72 + r * 72 + c) * 2),      \
                  kg + (size_t)((kt_) * 64 + r) * DH_ + c);                    \
        }                                                                      \
        cpcommit();                                                            \
    } while (0)
#define ISSUE_V(kt_, buf_)                                                     \
    do {                                                                       \
        _Pragma("unroll")                                                      \
        for (int t = 0; t < 2; t++) {                                          \
            const int s = tid + 256 * t;                                       \
            const int r = s >> 3, c = (s & 7) << 3;                            \
            cpa16(vs_s + (uint32_t)(((buf_) * 64 * 72 + r * 72 + c) * 2),      \
                  vg + (size_t)((kt_) * 64 + r) * DH_ + c);                    \
        }                                                                      \
        cpcommit();                                                            \
    } while (0)

    // Q (group), K0 (group), V0 (group)
#pragma unroll
    for (int t = 0; t < 4; t++) {
        const int s = tid + 256 * t;
        const int r = s >> 3, c = (s & 7) << 3;
        cpa16(qs_s + (uint32_t)((r * 72 + c) * 2), qg + (size_t)r * DH_ + c);
    }
    cpcommit();
    ISSUE_K(0, 0);
    ISSUE_V(0, 0);

    // ldmatrix lane addressing
    const int a_row = wq + (l & 15);
    const int a_col = (l >> 4) << 3;
    const int kb_row = ((l >> 4) << 3) + (l & 7);
    const int kb_col = ((l >> 3) & 1) << 3;
    const int vb_row = (((l >> 3) & 1) << 3) + (l & 7);
    const int vb_col = (l >> 4) << 3;

    cpwait<2>();
    __syncthreads();

    uint32_t qa[4][4];
    const uint32_t qaddr = qs_s + (uint32_t)((a_row * 72 + a_col) * 2);
#pragma unroll
    for (int kc = 0; kc < 4; kc++)
        ldsm4(qa[kc][0], qa[kc][1], qa[kc][2], qa[kc][3], qaddr + kc * 32);

    float4 ctx[8];
#pragma unroll
    for (int j = 0; j < 8; j++) ctx[j] = make_float4(0.f, 0.f, 0.f, 0.f);
    float rs0 = 0.f, rs1 = 0.f;

    const int rg0 = q0 + wq + g;
    const int rg1 = rg0 + 8;
    const int er0 = wq + g;            // local e rows
    __half* eg = g_eh + ((size_t)bh * L_ + q0) * L_;

    // mask prefetch for kt = 0
    uint64_t m0w = (*(const uint64_t*)(mbB + (size_t)rg0 * 256)) >> (2 * tig);
    uint64_t m1w = (*(const uint64_t*)(mbB + (size_t)rg1 * 256)) >> (2 * tig);

    for (int kt = 0; kt < 32; kt++) {
        const int buf = kt & 1;
        cpwait<1>();
        __syncthreads();

        // prefetch next iteration's mask words (resolve under QK MMAs)
        uint64_t n0w = 0, n1w = 0;
        if (kt + 1 < 32) {
            n0w = (*(const uint64_t*)(mbB + (size_t)rg0 * 256 + (kt + 1) * 8)) >> (2 * tig);
            n1w = (*(const uint64_t*)(mbB + (size_t)rg1 * 256 + (kt + 1) * 8)) >> (2 * tig);
        }

        // ---- QK^T ----
        float4 acc[8];
#pragma unroll
        for (int j = 0; j < 8; j++) acc[j] = make_float4(0.f, 0.f, 0.f, 0.f);

        const uint32_t ksb = ks_s + (uint32_t)(buf * 64 * 72 * 2);
#pragma unroll
        for (int kc = 0; kc < 4; kc++) {
#pragma unroll
            for (int q4 = 0; q4 < 4; q4++) {
                uint32_t b0, b1, b2, b3;
                ldsm4(b0, b1, b2, b3,
                      ksb + (uint32_t)(((q4 * 16 + kb_row) * 72 + kc * 16 + kb_col) * 2));
                mma_f16(acc[2 * q4],     qa[kc][0], qa[kc][1], qa[kc][2], qa[kc][3], b0, b1);
                mma_f16(acc[2 * q4 + 1], qa[kc][0], qa[kc][1], qa[kc][2], qa[kc][3], b2, b3);
            }
        }

        if (kt + 1 < 32) ISSUE_K(kt + 1, buf ^ 1);

        // ---- epilogue: bitmask exp -> es smem + register repack ----
        uint32_t plo[8], phi[8];
#pragma unroll
        for (int j = 0; j < 8; j++) {
            const unsigned t0 = (unsigned)(m0w >> (8 * j)) & 3u;
            const unsigned t1 = (unsigned)(m1w >> (8 * j)) & 3u;
            const float e0 = (t0 & 1u) ? exp2f(acc[j].x * LOG2E_DIV32) : 0.f;
            const float e1 = (t0 & 2u) ? exp2f(acc[j].y * LOG2E_DIV32) : 0.f;
            const float e2 = (t1 & 1u) ? exp2f(acc[j].z * LOG2E_DIV32) : 0.f;
            const float e3 = (t1 & 2u) ? exp2f(acc[j].w * LOG2E_DIV32) : 0.f;
            rs0 += e0 + e1;
            rs1 += e2 + e3;
            const __half2 h0 = __floats2half2_rn(e0, e1);
            const __half2 h1 = __floats2half2_rn(e2, e3);
            plo[j] = *(const uint32_t*)&h0;
            phi[j] = *(const uint32_t*)&h1;
            const int cl = 8 * j + 2 * tig;
            *(__half2*)&es[er0 * 72 + cl] = h0;
            *(__half2*)&es[(er0 + 8) * 72 + cl] = h1;
        }
        m0w = n0w;
        m1w = n1w;

        if (kt + 1 < 32) cpwait<1>(); else cpwait<0>();
        __syncthreads();   // publishes es + vs

        // ---- coalesced e tile store FIRST (drains under PV MMAs) ----
#pragma unroll
        for (int t = 0; t < 4; t++) {
            const int s = tid + 256 * t;
            const int r = s >> 3, c = (s & 7) << 3;
            __stcs((uint4*)(eg + (size_t)r * L_ + kt * 64 + c), *(const uint4*)&es[r * 72 + c]);
        }

        // ---- P @ V (A from registers) ----
        const uint32_t vsb = vs_s + (uint32_t)(buf * 64 * 72 * 2);
#pragma unroll
        for (int kc = 0; kc < 4; kc++) {
            const uint32_t a0 = plo[2 * kc], a1 = phi[2 * kc];
            const uint32_t a2 = plo[2 * kc + 1], a3 = phi[2 * kc + 1];
#pragma unroll
            for (int q4 = 0; q4 < 4; q4++) {
                uint32_t b0, b1, b2, b3;
                ldsm4t(b0, b1, b2, b3,
                       vsb + (uint32_t)(((kc * 16 + vb_row) * 72 + q4 * 16 + vb_col) * 2));
                mma_f16(ctx[2 * q4],     a0, a1, a2, a3, b0, b1);
                mma_f16(ctx[2 * q4 + 1], a0, a1, a2, a3, b2, b3);
            }
        }

        if (kt + 1 < 32) ISSUE_V(kt + 1, buf ^ 1);
    }

    // ---- rowsum reduce -> inv ----
    rs0 += __shfl_xor_sync(0xffffffffu, rs0, 1);
    rs0 += __shfl_xor_sync(0xffffffffu, rs0, 2);
    rs1 += __shfl_xor_sync(0xffffffffu, rs1, 1);
    rs1 += __shfl_xor_sync(0xffffffffu, rs1, 2);
    if (tig == 0) {
        red[wq + g] = rs0;
        red[wq + 8 + g] = rs1;
    }
    __syncthreads();
    if (tid < 128) {
        const float s = red[tid];
        const float iv = (s > 0.f) ? (1.f / s) : 0.f;
        g_inv[(size_t)bh * L_ + q0 + tid] = iv;
        red[tid] = iv;
    }
    __syncthreads();
    const float iv0 = red[wq + g];
    const float iv1 = red[wq + 8 + g];

    // ---- ctx write (normalized fp16) ----
#pragma unroll
    for (int j = 0; j < 8; j++) {
        const int cd = 8 * j + 2 * tig;
        *(__half2*)&g_ctxh[((size_t)bh * L_ + rg0) * DH_ + cd] =
            __floats2half2_rn(ctx[j].x * iv0, ctx[j].y * iv0);
        *(__half2*)&g_ctxh[((size_t)bh * L_ + rg1) * DH_ + cd] =
            __floats2half2_rn(ctx[j].z * iv1, ctx[j].w * iv1);
    }
    (void)dummy;
#undef ISSUE_K
#undef ISSUE_V
}

// ---------------------------------------------------------------------------
// Static side stream + events for graph fork/join (created once on the first
// uncaptured correctness call; captured graph is identical every call).
// ---------------------------------------------------------------------------
static cudaStream_t g_s2 = nullptr;
static cudaEvent_t g_evA, g_evB, g_evC, g_evD;

extern "C" void kernel_launch(void* const* d_in, const int* in_sizes, int n_in,
                              void* d_out, int out_size) {
    const float* Q  = (const float*)d_in[0];
    const float* K  = (const float*)d_in[1];
    const float* V  = (const float*)d_in[2];
    const int*   Mk = (const int*)d_in[3];
    const float* Wq = (const float*)d_in[4];
    const float* bq = (const float*)d_in[5];
    const float* Wk = (const float*)d_in[6];
    const float* bk = (const float*)d_in[7];
    const float* Wv = (const float*)d_in[8];
    const float* bv = (const float*)d_in[9];
    const float* Wo = (const float*)d_in[10];
    const float* bo = (const float*)d_in[11];

    float* out  = (float*)d_out;
    float* attn = out + OUT_ELEMS;   // concat(out, attn_dist)

    if (!g_s2) {
        cudaStreamCreateWithFlags(&g_s2, cudaStreamNonBlocking);
        cudaEventCreateWithFlags(&g_evA, cudaEventDisableTiming);
        cudaEventCreateWithFlags(&g_evB, cudaEventDisableTiming);
        cudaEventCreateWithFlags(&g_evC, cudaEventDisableTiming);
        cudaEventCreateWithFlags(&g_evD, cudaEventDisableTiming);
    }

    const int smem_gemm = (3 * 128 * 72 + 3 * 64 * 72) * 2;                  // 82944
    const int smem_attn = (128 * 72 + 4 * 64 * 72 + 128 * 72) * 2 + 128 * 4; // 74240
    cudaFuncSetAttribute(proj3, cudaFuncAttributeMaxDynamicSharedMemorySize, smem_gemm);
    cudaFuncSetAttribute(out_gemm, cudaFuncAttributeMaxDynamicSharedMemorySize, smem_gemm);
    cudaFuncSetAttribute(attn_fp16, cudaFuncAttributeMaxDynamicSharedMemorySize, smem_attn);

    // ---- fork 1: mask bitpack on side stream, converts+proj on main ----
    cudaEventRecord(g_evA, 0);
    cudaStreamWaitEvent(g_s2, g_evA, 0);
    pack_mask<<<2048, 256, 0, g_s2>>>(Mk);
    cudaEventRecord(g_evB, g_s2);

    convert_f2h<<<3 * 4096 + 4 * 256, 256>>>(Q, K, V, Wq, Wk, Wv, Wo);
    proj3<<<dim3(8, 64, 3), 256, smem_gemm>>>(bq, bk, bv);

    cudaStreamWaitEvent(0, g_evB, 0);   // join: attn needs mask + projections

    const dim3 ga(16, 32);   // q-tiles of 128, b*h
    attn_fp16<<<ga, 256, smem_attn>>>(attn);

    // ---- fork 2: out_gemm on side stream, rescale on main (independent) ----
    cudaEventRecord(g_evC, 0);
    cudaStreamWaitEvent(g_s2, g_evC, 0);
    out_gemm<<<dim3(8, 64), 256, smem_gemm, g_s2>>>(bo, out);
    cudaEventRecord(g_evD, g_s2);

    rescale_attn<<<B_ * H_ * L_ / 2, 256>>>(attn);

    cudaStreamWaitEvent(0, g_evD, 0);   // join before harness sync
}

// round 16
// speedup vs baseline: 1.0584x; 1.0157x over previous
#include <cuda_runtime.h>
#include <cuda_fp16.h>
#include <cstdint>

#define B_ 4
#define L_ 2048
#define D_ 512
#define H_ 8
#define DH_ 64
#define OUT_ELEMS (B_ * L_ * D_)          // 4194304
#define LOG2E_DIV32 0.04507129744f         // log2(e)/32  (folded into Q proj)

// Scratch (__device__ globals; allocation-free rule)
__device__ __half   g_qin[OUT_ELEMS];               // fp16 inputs
__device__ __half   g_kin[OUT_ELEMS];
__device__ __half   g_vin[OUT_ELEMS];
__device__ __half   g_wq[D_ * D_], g_wk[D_ * D_], g_wv[D_ * D_], g_wo[D_ * D_];
__device__ __half   g_qh[OUT_ELEMS];                // fp16 projections (Q pre-scaled)
__device__ __half   g_kh[OUT_ELEMS];
__device__ __half   g_vh[OUT_ELEMS];
__device__ __half   g_ctxh[OUT_ELEMS];              // fp16 attention context
__device__ float    g_inv[B_ * H_ * L_];
__device__ uint32_t g_maskb[(size_t)B_ * L_ * L_ / 32];   // 2 MB bitmask
__device__ __half   g_eh[(size_t)B_ * H_ * L_ * L_];      // 268 MB unnormalized e

// ---------------------------------------------------------------------------
// helpers
// ---------------------------------------------------------------------------
__device__ __forceinline__ void mma_f16(float4& d, uint32_t a0, uint32_t a1,
                                        uint32_t a2, uint32_t a3,
                                        uint32_t b0, uint32_t b1) {
    asm volatile(
        "mma.sync.aligned.m16n8k16.row.col.f32.f16.f16.f32 "
        "{%0,%1,%2,%3}, {%4,%5,%6,%7}, {%8,%9}, {%0,%1,%2,%3};"
        : "+f"(d.x), "+f"(d.y), "+f"(d.z), "+f"(d.w)
        : "r"(a0), "r"(a1), "r"(a2), "r"(a3), "r"(b0), "r"(b1));
}
__device__ __forceinline__ void ldsm4(uint32_t& r0, uint32_t& r1, uint32_t& r2,
                                      uint32_t& r3, uint32_t addr) {
    asm volatile("ldmatrix.sync.aligned.m8n8.x4.shared.b16 {%0,%1,%2,%3}, [%4];"
                 : "=r"(r0), "=r"(r1), "=r"(r2), "=r"(r3) : "r"(addr));
}
__device__ __forceinline__ void ldsm4t(uint32_t& r0, uint32_t& r1, uint32_t& r2,
                                       uint32_t& r3, uint32_t addr) {
    asm volatile("ldmatrix.sync.aligned.m8n8.x4.trans.shared.b16 {%0,%1,%2,%3}, [%4];"
                 : "=r"(r0), "=r"(r1), "=r"(r2), "=r"(r3) : "r"(addr));
}
__device__ __forceinline__ void cpa16(uint32_t s, const void* g) {
    asm volatile("cp.async.cg.shared.global [%0], [%1], 16;" :: "r"(s), "l"(g));
}
__device__ __forceinline__ void cpcommit() {
    asm volatile("cp.async.commit_group;" ::: "memory");
}
template <int N> __device__ __forceinline__ void cpwait() {
    asm volatile("cp.async.wait_group %0;" :: "n"(N) : "memory");
}

// ---------------------------------------------------------------------------
// pack_mask: mask int32 -> bitmask (warp ballot). 2048 blocks.
// ---------------------------------------------------------------------------
__global__ __launch_bounds__(256)
void pack_mask(const int* __restrict__ m) {
    const int wg = blockIdx.x * 8 + (threadIdx.x >> 5);
    const int lane = threadIdx.x & 31;
    const size_t base = (size_t)wg * 1024;
    uint32_t word = 0;
#pragma unroll
    for (int r = 0; r < 32; r++) {
        const int v = m[base + (size_t)r * 32 + lane];
        const unsigned bits = __ballot_sync(0xffffffffu, v != 0);
        if (lane == r) word = bits;
    }
    g_maskb[base / 32 + lane] = word;
}

// ---------------------------------------------------------------------------
// convert_f2h: Q,K,V + 4 weights fp32->fp16.
// ---------------------------------------------------------------------------
__global__ __launch_bounds__(256)
void convert_f2h(const float* __restrict__ Q, const float* __restrict__ K,
                 const float* __restrict__ V, const float* __restrict__ Wq,
                 const float* __restrict__ Wk, const float* __restrict__ Wv,
                 const float* __restrict__ Wo) {
    int bx = blockIdx.x;
    const float* s;
    __half* d;
    size_t i;
    if (bx < 3 * 4096) {
        const int seg = bx >> 12;
        const int b2 = bx & 4095;
        s = (seg == 0) ? Q : (seg == 1) ? K : V;
        d = (seg == 0) ? g_qin : (seg == 1) ? g_kin : g_vin;
        i = (size_t)b2 * 256 + threadIdx.x;
    } else {
        bx -= 3 * 4096;
        const int seg = bx >> 8;
        const int b2 = bx & 255;
        s = (seg == 0) ? Wq : (seg == 1) ? Wk : (seg == 2) ? Wv : Wo;
        d = (seg == 0) ? g_wq : (seg == 1) ? g_wk : (seg == 2) ? g_wv : g_wo;
        i = (size_t)b2 * 256 + threadIdx.x;
    }
    const float4 v = reinterpret_cast<const float4*>(s)[i];
    __half2 h0 = __floats2half2_rn(v.x, v.y);
    __half2 h1 = __floats2half2_rn(v.z, v.w);
    uint2 o;
    o.x = *(uint32_t*)&h0;
    o.y = *(uint32_t*)&h1;
    reinterpret_cast<uint2*>(d)[i] = o;
}

// ---------------------------------------------------------------------------
// fp16 GEMM body (3-stage cp.async ring). Block 128x64, 8 warps, warp 32x32.
// fp16 output path multiplies (acc + bias) by `scale` (1.0 for K/V/ctx;
// log2(e)/32 for Q so attn's exp2f needs no per-element FMUL).
// ---------------------------------------------------------------------------
__device__ __forceinline__ void hgemm_issue(const __half* A, const __half* W,
                                            int m0, int n0, uint32_t as_s,
                                            uint32_t bs_s, int ki, int buf,
                                            int tid) {
    const __half* Ap = A + (size_t)m0 * 512 + ki * 64;
#pragma unroll
    for (int t = 0; t < 4; t++) {
        const int s = tid + 256 * t;
        const int r = s >> 3, c = (s & 7) << 3;
        cpa16(as_s + (uint32_t)((buf * 128 * 72 + r * 72 + c) * 2),
              Ap + (size_t)r * 512 + c);
    }
    const __half* Wp = W + (size_t)ki * 64 * 512 + n0;
#pragma unroll
    for (int t = 0; t < 2; t++) {
        const int s = tid + 256 * t;
        const int r = s >> 3, c = (s & 7) << 3;
        cpa16(bs_s + (uint32_t)((buf * 64 * 72 + r * 72 + c) * 2),
              Wp + (size_t)r * 512 + c);
    }
    cpcommit();
}

template <typename OutT>
__device__ __forceinline__ void hgemm_body(const __half* __restrict__ A,
                                           const __half* __restrict__ W,
                                           const float* __restrict__ bias,
                                           OutT* __restrict__ C, float scale) {
    extern __shared__ __half smh[];
    __half* Ah = smh;                  // [3][128][72]
    __half* Wh = smh + 3 * 128 * 72;   // [3][64][72]

    const int tid = threadIdx.x, l = tid & 31, w = tid >> 5;
    const int mg = w >> 1, ng = w & 1;
    const int wm = mg * 32, wn = ng * 32;
    const int lr = l >> 2, lc = l & 3;
    const int m0 = blockIdx.y << 7, n0 = blockIdx.x << 6;

    const uint32_t as_s = (uint32_t)__cvta_generic_to_shared(Ah);
    const uint32_t bs_s = (uint32_t)__cvta_generic_to_shared(Wh);

    const int a_row = (l & 15), a_col = (l >> 4) << 3;
    const int vb_row = (((l >> 3) & 1) << 3) + (l & 7);
    const int vb_col = (l >> 4) << 3;

    float4 acc[2][4];
#pragma unroll
    for (int m = 0; m < 2; m++)
#pragma unroll
        for (int j = 0; j < 4; j++) acc[m][j] = make_float4(0.f, 0.f, 0.f, 0.f);

    hgemm_issue(A, W, m0, n0, as_s, bs_s, 0, 0, tid);
    hgemm_issue(A, W, m0, n0, as_s, bs_s, 1, 1, tid);

    for (int ki = 0; ki < 8; ki++) {
        if (ki + 2 < 8) {
            hgemm_issue(A, W, m0, n0, as_s, bs_s, ki + 2, (ki + 2) % 3, tid);
            cpwait<2>();
        } else if (ki == 6) {
            cpwait<1>();
        } else {
            cpwait<0>();
        }
        __syncthreads();

        const int buf = ki % 3;
        const uint32_t a0b = as_s + (uint32_t)((buf * 128 * 72 + (wm + a_row) * 72 + a_col) * 2);
        const uint32_t a1b = a0b + 16 * 72 * 2;
        const uint32_t wb = bs_s + (uint32_t)((buf * 64 * 72) * 2);

#pragma unroll
        for (int kc = 0; kc < 4; kc++) {
            uint32_t a0[4], a1[4];
            ldsm4(a0[0], a0[1], a0[2], a0[3], a0b + kc * 32);
            ldsm4(a1[0], a1[1], a1[2], a1[3], a1b + kc * 32);
#pragma unroll
            for (int j = 0; j < 2; j++) {
                uint32_t b0, b1, b2, b3;
                ldsm4t(b0, b1, b2, b3,
                       wb + (uint32_t)(((kc * 16 + vb_row) * 72 + wn + 16 * j + vb_col) * 2));
                mma_f16(acc[0][2 * j],     a0[0], a0[1], a0[2], a0[3], b0, b1);
                mma_f16(acc[1][2 * j],     a1[0], a1[1], a1[2], a1[3], b0, b1);
                mma_f16(acc[0][2 * j + 1], a0[0], a0[1], a0[2], a0[3], b2, b3);
                mma_f16(acc[1][2 * j + 1], a1[0], a1[1], a1[2], a1[3], b2, b3);
            }
        }
        __syncthreads();
    }

#pragma unroll
    for (int m = 0; m < 2; m++)
#pragma unroll
        for (int j = 0; j < 4; j++) {
            const int rg = m0 + wm + 16 * m + lr;
            const int cg = n0 + wn + 8 * j + 2 * lc;
            const float2 bv = *(const float2*)&bias[cg];
            if constexpr (sizeof(OutT) == 2) {
                *(__half2*)&C[(size_t)rg * 512 + cg] =
                    __floats2half2_rn((acc[m][j].x + bv.x) * scale,
                                      (acc[m][j].y + bv.y) * scale);
                *(__half2*)&C[(size_t)(rg + 8) * 512 + cg] =
                    __floats2half2_rn((acc[m][j].z + bv.x) * scale,
                                      (acc[m][j].w + bv.y) * scale);
            } else {
                *(float2*)&C[(size_t)rg * 512 + cg] =
                    make_float2(acc[m][j].x + bv.x, acc[m][j].y + bv.y);
                *(float2*)&C[(size_t)(rg + 8) * 512 + cg] =
                    make_float2(acc[m][j].z + bv.x, acc[m][j].w + bv.y);
            }
        }
}

__global__ __launch_bounds__(256, 2)
void proj3(const float* __restrict__ bq, const float* __restrict__ bk,
           const float* __restrict__ bv) {
    if (blockIdx.z == 0)      hgemm_body<__half>(g_qin, g_wq, bq, g_qh, LOG2E_DIV32);
    else if (blockIdx.z == 1) hgemm_body<__half>(g_kin, g_wk, bk, g_kh, 1.0f);
    else                      hgemm_body<__half>(g_vin, g_wv, bv, g_vh, 1.0f);
}

__global__ __launch_bounds__(256, 2)
void out_gemm(const float* __restrict__ bo, float* __restrict__ out) {
    hgemm_body<float>(g_ctxh, g_wo, bo, out, 1.0f);
}

// ---------------------------------------------------------------------------
// rescale: attn[row][:] = fp32(g_eh[row][:]) * g_inv[row]. 2 rows/block.
// ---------------------------------------------------------------------------
__global__ __launch_bounds__(256)
void rescale_attn(float* __restrict__ attn) {
    const int row0 = blockIdx.x * 2;
    const int row1 = row0 + 1;
    const float iv0 = g_inv[row0];
    const float iv1 = g_inv[row1];
    const int tid = threadIdx.x;
    const uint4 u0 = __ldcs(&reinterpret_cast<const uint4*>(g_eh + (size_t)row0 * L_)[tid]);
    const uint4 u1 = __ldcs(&reinterpret_cast<const uint4*>(g_eh + (size_t)row1 * L_)[tid]);

    float4* d0 = reinterpret_cast<float4*>(attn + (size_t)row0 * L_);
    float4* d1 = reinterpret_cast<float4*>(attn + (size_t)row1 * L_);
    {
        const float2 f0 = __half22float2(*(const __half2*)&u0.x);
        const float2 f1 = __half22float2(*(const __half2*)&u0.y);
        const float2 f2 = __half22float2(*(const __half2*)&u0.z);
        const float2 f3 = __half22float2(*(const __half2*)&u0.w);
        __stcs(&d0[2 * tid],     make_float4(f0.x * iv0, f0.y * iv0, f1.x * iv0, f1.y * iv0));
        __stcs(&d0[2 * tid + 1], make_float4(f2.x * iv0, f2.y * iv0, f3.x * iv0, f3.y * iv0));
    }
    {
        const float2 f0 = __half22float2(*(const __half2*)&u1.x);
        const float2 f1 = __half22float2(*(const __half2*)&u1.y);
        const float2 f2 = __half22float2(*(const __half2*)&u1.z);
        const float2 f3 = __half22float2(*(const __half2*)&u1.w);
        __stcs(&d1[2 * tid],     make_float4(f0.x * iv1, f0.y * iv1, f1.x * iv1, f1.y * iv1));
        __stcs(&d1[2 * tid + 1], make_float4(f2.x * iv1, f2.y * iv1, f3.x * iv1, f3.y * iv1));
    }
}

// ---------------------------------------------------------------------------
// fp16 fused attention. Q pre-scaled by log2(e)/32 -> epilogue is bare exp2f.
// ---------------------------------------------------------------------------
__global__ __launch_bounds__(256, 2)
void attn_fp16(float* __restrict__ dummy) {
    extern __shared__ __half smh[];
    __half* qs = smh;                  // [128][72]
    __half* ks = qs + 128 * 72;        // [2][64][72]
    __half* vs = ks + 2 * 64 * 72;     // [2][64][72]
    __half* es = vs + 2 * 64 * 72;     // [128][72] (64 cols used)
    float* red = (float*)(es + 128 * 72);   // [128]

    const int tid = threadIdx.x, l = tid & 31, w = tid >> 5;
    const int wq = w * 16;
    const int g = l >> 2, tig = l & 3;
    const int qt = blockIdx.x, bh = blockIdx.y, b = bh >> 3;
    const int q0 = qt * 128;

    const __half* qg = g_qh + ((size_t)bh * L_ + q0) * DH_;
    const __half* kg = g_kh + (size_t)bh * L_ * DH_;
    const __half* vg = g_vh + (size_t)bh * L_ * DH_;
    const uint8_t* mbB = (const uint8_t*)g_maskb + ((size_t)b * L_ * L_ >> 3);

    const uint32_t qs_s = (uint32_t)__cvta_generic_to_shared(qs);
    const uint32_t ks_s = (uint32_t)__cvta_generic_to_shared(ks);
    const uint32_t vs_s = (uint32_t)__cvta_generic_to_shared(vs);

#define ISSUE_K(kt_, buf_)                                                     \
    do {                                                                       \
        _Pragma("unroll")                                                      \
        for (int t = 0; t < 2; t++) {                                          \
            const int s = tid + 256 * t;                                       \
            const int r = s >> 3, c = (s & 7) << 3;                            \
            cpa16(ks_s + (uint32_t)(((buf_) * 64 * 72 + r * 72 + c) * 2),      \
                  kg + (size_t)((kt_) * 64 + r) * DH_ + c);                    \
        }                                                                      \
        cpcommit();                                                            \
    } while (0)
#define ISSUE_V(kt_, buf_)                                                     \
    do {                                                                       \
        _Pragma("unroll")                                                      \
        for (int t = 0; t < 2; t++) {                                          \
            const int s = tid + 256 * t;                                       \
            const int r = s >> 3, c = (s & 7) << 3;                            \
            cpa16(vs_s + (uint32_t)(((buf_) * 64 * 72 + r * 72 + c) * 2),      \
                  vg + (size_t)((kt_) * 64 + r) * DH_ + c);                    \
        }                                                                      \
        cpcommit();                                                            \
    } while (0)

    // Q (group), K0 (group), V0 (group)
#pragma unroll
    for (int t = 0; t < 4; t++) {
        const int s = tid + 256 * t;
        const int r = s >> 3, c = (s & 7) << 3;
        cpa16(qs_s + (uint32_t)((r * 72 + c) * 2), qg + (size_t)r * DH_ + c);
    }
    cpcommit();
    ISSUE_K(0, 0);
    ISSUE_V(0, 0);

    // ldmatrix lane addressing
    const int a_row = wq + (l & 15);
    const int a_col = (l >> 4) << 3;
    const int kb_row = ((l >> 4) << 3) + (l & 7);
    const int kb_col = ((l >> 3) & 1) << 3;
    const int vb_row = (((l >> 3) & 1) << 3) + (l & 7);
    const int vb_col = (l >> 4) << 3;

    cpwait<2>();
    __syncthreads();

    uint32_t qa[4][4];
    const uint32_t qaddr = qs_s + (uint32_t)((a_row * 72 + a_col) * 2);
#pragma unroll
    for (int kc = 0; kc < 4; kc++)
        ldsm4(qa[kc][0], qa[kc][1], qa[kc][2], qa[kc][3], qaddr + kc * 32);

    float4 ctx[8];
#pragma unroll
    for (int j = 0; j < 8; j++) ctx[j] = make_float4(0.f, 0.f, 0.f, 0.f);
    float rs0 = 0.f, rs1 = 0.f;

    const int rg0 = q0 + wq + g;
    const int rg1 = rg0 + 8;
    const int er0 = wq + g;            // local e rows
    __half* eg = g_eh + ((size_t)bh * L_ + q0) * L_;

    // mask prefetch for kt = 0
    uint64_t m0w = (*(const uint64_t*)(mbB + (size_t)rg0 * 256)) >> (2 * tig);
    uint64_t m1w = (*(const uint64_t*)(mbB + (size_t)rg1 * 256)) >> (2 * tig);

    for (int kt = 0; kt < 32; kt++) {
        const int buf = kt & 1;
        cpwait<1>();
        __syncthreads();

        // prefetch next iteration's mask words (resolve under QK MMAs)
        uint64_t n0w = 0, n1w = 0;
        if (kt + 1 < 32) {
            n0w = (*(const uint64_t*)(mbB + (size_t)rg0 * 256 + (kt + 1) * 8)) >> (2 * tig);
            n1w = (*(const uint64_t*)(mbB + (size_t)rg1 * 256 + (kt + 1) * 8)) >> (2 * tig);
        }

        // ---- QK^T ----
        float4 acc[8];
#pragma unroll
        for (int j = 0; j < 8; j++) acc[j] = make_float4(0.f, 0.f, 0.f, 0.f);

        const uint32_t ksb = ks_s + (uint32_t)(buf * 64 * 72 * 2);
#pragma unroll
        for (int kc = 0; kc < 4; kc++) {
#pragma unroll
            for (int q4 = 0; q4 < 4; q4++) {
                uint32_t b0, b1, b2, b3;
                ldsm4(b0, b1, b2, b3,
                      ksb + (uint32_t)(((q4 * 16 + kb_row) * 72 + kc * 16 + kb_col) * 2));
                mma_f16(acc[2 * q4],     qa[kc][0], qa[kc][1], qa[kc][2], qa[kc][3], b0, b1);
                mma_f16(acc[2 * q4 + 1], qa[kc][0], qa[kc][1], qa[kc][2], qa[kc][3], b2, b3);
            }
        }

        if (kt + 1 < 32) ISSUE_K(kt + 1, buf ^ 1);

        // ---- epilogue: bitmask exp2 (Q pre-scaled) -> es smem + repack ----
        uint32_t plo[8], phi[8];
#pragma unroll
        for (int j = 0; j < 8; j++) {
            const unsigned t0 = (unsigned)(m0w >> (8 * j)) & 3u;
            const unsigned t1 = (unsigned)(m1w >> (8 * j)) & 3u;
            const float e0 = (t0 & 1u) ? exp2f(acc[j].x) : 0.f;
            const float e1 = (t0 & 2u) ? exp2f(acc[j].y) : 0.f;
            const float e2 = (t1 & 1u) ? exp2f(acc[j].z) : 0.f;
            const float e3 = (t1 & 2u) ? exp2f(acc[j].w) : 0.f;
            rs0 += e0 + e1;
            rs1 += e2 + e3;
            const __half2 h0 = __floats2half2_rn(e0, e1);
            const __half2 h1 = __floats2half2_rn(e2, e3);
            plo[j] = *(const uint32_t*)&h0;
            phi[j] = *(const uint32_t*)&h1;
            const int cl = 8 * j + 2 * tig;
            *(__half2*)&es[er0 * 72 + cl] = h0;
            *(__half2*)&es[(er0 + 8) * 72 + cl] = h1;
        }
        m0w = n0w;
        m1w = n1w;

        if (kt + 1 < 32) cpwait<1>(); else cpwait<0>();
        __syncthreads();   // publishes es + vs

        // ---- coalesced e tile store FIRST (drains under PV MMAs) ----
#pragma unroll
        for (int t = 0; t < 4; t++) {
            const int s = tid + 256 * t;
            const int r = s >> 3, c = (s & 7) << 3;
            __stcs((uint4*)(eg + (size_t)r * L_ + kt * 64 + c), *(const uint4*)&es[r * 72 + c]);
        }

        // ---- P @ V (A from registers) ----
        const uint32_t vsb = vs_s + (uint32_t)(buf * 64 * 72 * 2);
#pragma unroll
        for (int kc = 0; kc < 4; kc++) {
            const uint32_t a0 = plo[2 * kc], a1 = phi[2 * kc];
            const uint32_t a2 = plo[2 * kc + 1], a3 = phi[2 * kc + 1];
#pragma unroll
            for (int q4 = 0; q4 < 4; q4++) {
                uint32_t b0, b1, b2, b3;
                ldsm4t(b0, b1, b2, b3,
                       vsb + (uint32_t)(((kc * 16 + vb_row) * 72 + q4 * 16 + vb_col) * 2));
                mma_f16(ctx[2 * q4],     a0, a1, a2, a3, b0, b1);
                mma_f16(ctx[2 * q4 + 1], a0, a1, a2, a3, b2, b3);
            }
        }

        if (kt + 1 < 32) ISSUE_V(kt + 1, buf ^ 1);
    }

    // ---- rowsum reduce -> inv ----
    rs0 += __shfl_xor_sync(0xffffffffu, rs0, 1);
    rs0 += __shfl_xor_sync(0xffffffffu, rs0, 2);
    rs1 += __shfl_xor_sync(0xffffffffu, rs1, 1);
    rs1 += __shfl_xor_sync(0xffffffffu, rs1, 2);
    if (tig == 0) {
        red[wq + g] = rs0;
        red[wq + 8 + g] = rs1;
    }
    __syncthreads();
    if (tid < 128) {
        const float s = red[tid];
        const float iv = (s > 0.f) ? (1.f / s) : 0.f;
        g_inv[(size_t)bh * L_ + q0 + tid] = iv;
        red[tid] = iv;
    }
    __syncthreads();
    const float iv0 = red[wq + g];
    const float iv1 = red[wq + 8 + g];

    // ---- ctx write (normalized fp16) ----
#pragma unroll
    for (int j = 0; j < 8; j++) {
        const int cd = 8 * j + 2 * tig;
        *(__half2*)&g_ctxh[((size_t)bh * L_ + rg0) * DH_ + cd] =
            __floats2half2_rn(ctx[j].x * iv0, ctx[j].y * iv0);
        *(__half2*)&g_ctxh[((size_t)bh * L_ + rg1) * DH_ + cd] =
            __floats2half2_rn(ctx[j].z * iv1, ctx[j].w * iv1);
    }
    (void)dummy;
#undef ISSUE_K
#undef ISSUE_V
}

// ---------------------------------------------------------------------------
// Static side stream + events for graph fork/join.
// ---------------------------------------------------------------------------
static cudaStream_t g_s2 = nullptr;
static cudaEvent_t g_evA, g_evB, g_evC, g_evD;

extern "C" void kernel_launch(void* const* d_in, const int* in_sizes, int n_in,
                              void* d_out, int out_size) {
    const float* Q  = (const float*)d_in[0];
    const float* K  = (const float*)d_in[1];
    const float* V  = (const float*)d_in[2];
    const int*   Mk = (const int*)d_in[3];
    const float* Wq = (const float*)d_in[4];
    const float* bq = (const float*)d_in[5];
    const float* Wk = (const float*)d_in[6];
    const float* bk = (const float*)d_in[7];
    const float* Wv = (const float*)d_in[8];
    const float* bv = (const float*)d_in[9];
    const float* Wo = (const float*)d_in[10];
    const float* bo = (const float*)d_in[11];

    float* out  = (float*)d_out;
    float* attn = out + OUT_ELEMS;   // concat(out, attn_dist)

    if (!g_s2) {
        cudaStreamCreateWithFlags(&g_s2, cudaStreamNonBlocking);
        cudaEventCreateWithFlags(&g_evA, cudaEventDisableTiming);
        cudaEventCreateWithFlags(&g_evB, cudaEventDisableTiming);
        cudaEventCreateWithFlags(&g_evC, cudaEventDisableTiming);
        cudaEventCreateWithFlags(&g_evD, cudaEventDisableTiming);
    }

    const int smem_gemm = (3 * 128 * 72 + 3 * 64 * 72) * 2;                  // 82944
    const int smem_attn = (128 * 72 + 4 * 64 * 72 + 128 * 72) * 2 + 128 * 4; // 74240
    cudaFuncSetAttribute(proj3, cudaFuncAttributeMaxDynamicSharedMemorySize, smem_gemm);
    cudaFuncSetAttribute(out_gemm, cudaFuncAttributeMaxDynamicSharedMemorySize, smem_gemm);
    cudaFuncSetAttribute(attn_fp16, cudaFuncAttributeMaxDynamicSharedMemorySize, smem_attn);

    // ---- fork 1: mask bitpack on side stream, converts+proj on main ----
    cudaEventRecord(g_evA, 0);
    cudaStreamWaitEvent(g_s2, g_evA, 0);
    pack_mask<<<2048, 256, 0, g_s2>>>(Mk);
    cudaEventRecord(g_evB, g_s2);

    convert_f2h<<<3 * 4096 + 4 * 256, 256>>>(Q, K, V, Wq, Wk, Wv, Wo);
    proj3<<<dim3(8, 64, 3), 256, smem_gemm>>>(bq, bk, bv);

    cudaStreamWaitEvent(0, g_evB, 0);   // join: attn needs mask + projections

    const dim3 ga(16, 32);   // q-tiles of 128, b*h
    attn_fp16<<<ga, 256, smem_attn>>>(attn);

    // ---- fork 2: out_gemm on side stream, rescale on main (independent) ----
    cudaEventRecord(g_evC, 0);
    cudaStreamWaitEvent(g_s2, g_evC, 0);
    out_gemm<<<dim3(8, 64), 256, smem_gemm, g_s2>>>(bo, out);
    cudaEventRecord(g_evD, g_s2);

    rescale_attn<<<B_ * H_ * L_ / 2, 256>>>(attn);

    cudaStreamWaitEvent(0, g_evD, 0);   // join before harness sync
}

// round 17
// speedup vs baseline: 1.0940x; 1.0337x over previous
#include <cuda_runtime.h>
#include <cuda_fp16.h>
#include <cstdint>

#define B_ 4
#define L_ 2048
#define D_ 512
#define H_ 8
#define DH_ 64
#define OUT_ELEMS (B_ * L_ * D_)          // 4194304
#define LOG2E_DIV32 0.04507129744f         // log2(e)/32  (folded into Q proj)

// Scratch (__device__ globals; allocation-free rule)
__device__ __half   g_qin[OUT_ELEMS];
__device__ __half   g_kin[OUT_ELEMS];
__device__ __half   g_vin[OUT_ELEMS];
__device__ __half   g_wq[D_ * D_], g_wk[D_ * D_], g_wv[D_ * D_], g_wo[D_ * D_];
__device__ __half   g_qh[OUT_ELEMS];                // Q pre-scaled by log2e/32
__device__ __half   g_kh[OUT_ELEMS];
__device__ __half   g_vh[OUT_ELEMS];
__device__ __half   g_ctxh[OUT_ELEMS];
__device__ float    g_inv[B_ * H_ * L_];
__device__ uint32_t g_maskb[(size_t)B_ * L_ * L_ / 32];   // 2 MB bitmask
__device__ __half   g_eh[(size_t)B_ * H_ * L_ * L_];      // 268 MB unnormalized e

// ---------------------------------------------------------------------------
// helpers
// ---------------------------------------------------------------------------
__device__ __forceinline__ void mma_f16(float4& d, uint32_t a0, uint32_t a1,
                                        uint32_t a2, uint32_t a3,
                                        uint32_t b0, uint32_t b1) {
    asm volatile(
        "mma.sync.aligned.m16n8k16.row.col.f32.f16.f16.f32 "
        "{%0,%1,%2,%3}, {%4,%5,%6,%7}, {%8,%9}, {%0,%1,%2,%3};"
        : "+f"(d.x), "+f"(d.y), "+f"(d.z), "+f"(d.w)
        : "r"(a0), "r"(a1), "r"(a2), "r"(a3), "r"(b0), "r"(b1));
}
__device__ __forceinline__ void ldsm4(uint32_t& r0, uint32_t& r1, uint32_t& r2,
                                      uint32_t& r3, uint32_t addr) {
    asm volatile("ldmatrix.sync.aligned.m8n8.x4.shared.b16 {%0,%1,%2,%3}, [%4];"
                 : "=r"(r0), "=r"(r1), "=r"(r2), "=r"(r3) : "r"(addr));
}
__device__ __forceinline__ void ldsm4t(uint32_t& r0, uint32_t& r1, uint32_t& r2,
                                       uint32_t& r3, uint32_t addr) {
    asm volatile("ldmatrix.sync.aligned.m8n8.x4.trans.shared.b16 {%0,%1,%2,%3}, [%4];"
                 : "=r"(r0), "=r"(r1), "=r"(r2), "=r"(r3) : "r"(addr));
}
__device__ __forceinline__ void cpa16(uint32_t s, const void* g) {
    asm volatile("cp.async.cg.shared.global [%0], [%1], 16;" :: "r"(s), "l"(g));
}
__device__ __forceinline__ void cpcommit() {
    asm volatile("cp.async.commit_group;" ::: "memory");
}
template <int N> __device__ __forceinline__ void cpwait() {
    asm volatile("cp.async.wait_group %0;" :: "n"(N) : "memory");
}

// ---------------------------------------------------------------------------
// pack_mask: mask int32 -> bitmask (warp ballot). 2048 blocks.
// ---------------------------------------------------------------------------
__global__ __launch_bounds__(256)
void pack_mask(const int* __restrict__ m) {
    const int wg = blockIdx.x * 8 + (threadIdx.x >> 5);
    const int lane = threadIdx.x & 31;
    const size_t base = (size_t)wg * 1024;
    uint32_t word = 0;
#pragma unroll
    for (int r = 0; r < 32; r++) {
        const int v = m[base + (size_t)r * 32 + lane];
        const unsigned bits = __ballot_sync(0xffffffffu, v != 0);
        if (lane == r) word = bits;
    }
    g_maskb[base / 32 + lane] = word;
}

// ---------------------------------------------------------------------------
// convert_f2h: Q,K,V + 4 weights fp32->fp16.
// ---------------------------------------------------------------------------
__global__ __launch_bounds__(256)
void convert_f2h(const float* __restrict__ Q, const float* __restrict__ K,
                 const float* __restrict__ V, const float* __restrict__ Wq,
                 const float* __restrict__ Wk, const float* __restrict__ Wv,
                 const float* __restrict__ Wo) {
    int bx = blockIdx.x;
    const float* s;
    __half* d;
    size_t i;
    if (bx < 3 * 4096) {
        const int seg = bx >> 12;
        const int b2 = bx & 4095;
        s = (seg == 0) ? Q : (seg == 1) ? K : V;
        d = (seg == 0) ? g_qin : (seg == 1) ? g_kin : g_vin;
        i = (size_t)b2 * 256 + threadIdx.x;
    } else {
        bx -= 3 * 4096;
        const int seg = bx >> 8;
        const int b2 = bx & 255;
        s = (seg == 0) ? Wq : (seg == 1) ? Wk : (seg == 2) ? Wv : Wo;
        d = (seg == 0) ? g_wq : (seg == 1) ? g_wk : (seg == 2) ? g_wv : g_wo;
        i = (size_t)b2 * 256 + threadIdx.x;
    }
    const float4 v = reinterpret_cast<const float4*>(s)[i];
    __half2 h0 = __floats2half2_rn(v.x, v.y);
    __half2 h1 = __floats2half2_rn(v.z, v.w);
    uint2 o;
    o.x = *(uint32_t*)&h0;
    o.y = *(uint32_t*)&h1;
    reinterpret_cast<uint2*>(d)[i] = o;
}

// ---------------------------------------------------------------------------
// fp16 GEMM body (3-stage cp.async ring). Block 128x64, 8 warps, warp 32x32.
// ---------------------------------------------------------------------------
__device__ __forceinline__ void hgemm_issue(const __half* A, const __half* W,
                                            int m0, int n0, uint32_t as_s,
                                            uint32_t bs_s, int ki, int buf,
                                            int tid) {
    const __half* Ap = A + (size_t)m0 * 512 + ki * 64;
#pragma unroll
    for (int t = 0; t < 4; t++) {
        const int s = tid + 256 * t;
        const int r = s >> 3, c = (s & 7) << 3;
        cpa16(as_s + (uint32_t)((buf * 128 * 72 + r * 72 + c) * 2),
              Ap + (size_t)r * 512 + c);
    }
    const __half* Wp = W + (size_t)ki * 64 * 512 + n0;
#pragma unroll
    for (int t = 0; t < 2; t++) {
        const int s = tid + 256 * t;
        const int r = s >> 3, c = (s & 7) << 3;
        cpa16(bs_s + (uint32_t)((buf * 64 * 72 + r * 72 + c) * 2),
              Wp + (size_t)r * 512 + c);
    }
    cpcommit();
}

template <typename OutT>
__device__ __forceinline__ void hgemm_body(const __half* __restrict__ A,
                                           const __half* __restrict__ W,
                                           const float* __restrict__ bias,
                                           OutT* __restrict__ C, float scale) {
    extern __shared__ __half smh[];
    __half* Ah = smh;                  // [3][128][72]
    __half* Wh = smh + 3 * 128 * 72;   // [3][64][72]

    const int tid = threadIdx.x, l = tid & 31, w = tid >> 5;
    const int mg = w >> 1, ng = w & 1;
    const int wm = mg * 32, wn = ng * 32;
    const int lr = l >> 2, lc = l & 3;
    const int m0 = blockIdx.y << 7, n0 = blockIdx.x << 6;

    const uint32_t as_s = (uint32_t)__cvta_generic_to_shared(Ah);
    const uint32_t bs_s = (uint32_t)__cvta_generic_to_shared(Wh);

    const int a_row = (l & 15), a_col = (l >> 4) << 3;
    const int vb_row = (((l >> 3) & 1) << 3) + (l & 7);
    const int vb_col = (l >> 4) << 3;

    float4 acc[2][4];
#pragma unroll
    for (int m = 0; m < 2; m++)
#pragma unroll
        for (int j = 0; j < 4; j++) acc[m][j] = make_float4(0.f, 0.f, 0.f, 0.f);

    hgemm_issue(A, W, m0, n0, as_s, bs_s, 0, 0, tid);
    hgemm_issue(A, W, m0, n0, as_s, bs_s, 1, 1, tid);

    for (int ki = 0; ki < 8; ki++) {
        if (ki + 2 < 8) {
            hgemm_issue(A, W, m0, n0, as_s, bs_s, ki + 2, (ki + 2) % 3, tid);
            cpwait<2>();
        } else if (ki == 6) {
            cpwait<1>();
        } else {
            cpwait<0>();
        }
        __syncthreads();

        const int buf = ki % 3;
        const uint32_t a0b = as_s + (uint32_t)((buf * 128 * 72 + (wm + a_row) * 72 + a_col) * 2);
        const uint32_t a1b = a0b + 16 * 72 * 2;
        const uint32_t wb = bs_s + (uint32_t)((buf * 64 * 72) * 2);

#pragma unroll
        for (int kc = 0; kc < 4; kc++) {
            uint32_t a0[4], a1[4];
            ldsm4(a0[0], a0[1], a0[2], a0[3], a0b + kc * 32);
            ldsm4(a1[0], a1[1], a1[2], a1[3], a1b + kc * 32);
#pragma unroll
            for (int j = 0; j < 2; j++) {
                uint32_t b0, b1, b2, b3;
                ldsm4t(b0, b1, b2, b3,
                       wb + (uint32_t)(((kc * 16 + vb_row) * 72 + wn + 16 * j + vb_col) * 2));
                mma_f16(acc[0][2 * j],     a0[0], a0[1], a0[2], a0[3], b0, b1);
                mma_f16(acc[1][2 * j],     a1[0], a1[1], a1[2], a1[3], b0, b1);
                mma_f16(acc[0][2 * j + 1], a0[0], a0[1], a0[2], a0[3], b2, b3);
                mma_f16(acc[1][2 * j + 1], a1[0], a1[1], a1[2], a1[3], b2, b3);
            }
        }
        __syncthreads();
    }

#pragma unroll
    for (int m = 0; m < 2; m++)
#pragma unroll
        for (int j = 0; j < 4; j++) {
            const int rg = m0 + wm + 16 * m + lr;
            const int cg = n0 + wn + 8 * j + 2 * lc;
            const float2 bv = *(const float2*)&bias[cg];
            if constexpr (sizeof(OutT) == 2) {
                *(__half2*)&C[(size_t)rg * 512 + cg] =
                    __floats2half2_rn((acc[m][j].x + bv.x) * scale,
                                      (acc[m][j].y + bv.y) * scale);
                *(__half2*)&C[(size_t)(rg + 8) * 512 + cg] =
                    __floats2half2_rn((acc[m][j].z + bv.x) * scale,
                                      (acc[m][j].w + bv.y) * scale);
            } else {
                *(float2*)&C[(size_t)rg * 512 + cg] =
                    make_float2(acc[m][j].x + bv.x, acc[m][j].y + bv.y);
                *(float2*)&C[(size_t)(rg + 8) * 512 + cg] =
                    make_float2(acc[m][j].z + bv.x, acc[m][j].w + bv.y);
            }
        }
}

__global__ __launch_bounds__(256, 2)
void proj3(const float* __restrict__ bq, const float* __restrict__ bk,
           const float* __restrict__ bv) {
    if (blockIdx.z == 0)      hgemm_body<__half>(g_qin, g_wq, bq, g_qh, LOG2E_DIV32);
    else if (blockIdx.z == 1) hgemm_body<__half>(g_kin, g_wk, bk, g_kh, 1.0f);
    else                      hgemm_body<__half>(g_vin, g_wv, bv, g_vh, 1.0f);
}

__global__ __launch_bounds__(256, 2)
void out_gemm(const float* __restrict__ bo, float* __restrict__ out) {
    hgemm_body<float>(g_ctxh, g_wo, bo, out, 1.0f);
}

// ---------------------------------------------------------------------------
// rescale (half-range): rows [row_base, row_base + 32768). 2 rows/block.
// ---------------------------------------------------------------------------
__global__ __launch_bounds__(256)
void rescale_attn(float* __restrict__ attn, int row_base) {
    const int row0 = row_base + blockIdx.x * 2;
    const int row1 = row0 + 1;
    const float iv0 = g_inv[row0];
    const float iv1 = g_inv[row1];
    const int tid = threadIdx.x;
    const uint4 u0 = __ldcs(&reinterpret_cast<const uint4*>(g_eh + (size_t)row0 * L_)[tid]);
    const uint4 u1 = __ldcs(&reinterpret_cast<const uint4*>(g_eh + (size_t)row1 * L_)[tid]);

    float4* d0 = reinterpret_cast<float4*>(attn + (size_t)row0 * L_);
    float4* d1 = reinterpret_cast<float4*>(attn + (size_t)row1 * L_);
    {
        const float2 f0 = __half22float2(*(const __half2*)&u0.x);
        const float2 f1 = __half22float2(*(const __half2*)&u0.y);
        const float2 f2 = __half22float2(*(const __half2*)&u0.z);
        const float2 f3 = __half22float2(*(const __half2*)&u0.w);
        __stcs(&d0[2 * tid],     make_float4(f0.x * iv0, f0.y * iv0, f1.x * iv0, f1.y * iv0));
        __stcs(&d0[2 * tid + 1], make_float4(f2.x * iv0, f2.y * iv0, f3.x * iv0, f3.y * iv0));
    }
    {
        const float2 f0 = __half22float2(*(const __half2*)&u1.x);
        const float2 f1 = __half22float2(*(const __half2*)&u1.y);
        const float2 f2 = __half22float2(*(const __half2*)&u1.z);
        const float2 f3 = __half22float2(*(const __half2*)&u1.w);
        __stcs(&d1[2 * tid],     make_float4(f0.x * iv1, f0.y * iv1, f1.x * iv1, f1.y * iv1));
        __stcs(&d1[2 * tid + 1], make_float4(f2.x * iv1, f2.y * iv1, f3.x * iv1, f3.y * iv1));
    }
}

// ---------------------------------------------------------------------------
// fp16 fused attention (half-range over bh): bh = bh0 + blockIdx.y.
// ---------------------------------------------------------------------------
__global__ __launch_bounds__(256, 2)
void attn_fp16(float* __restrict__ dummy, int bh0) {
    extern __shared__ __half smh[];
    __half* qs = smh;                  // [128][72]
    __half* ks = qs + 128 * 72;        // [2][64][72]
    __half* vs = ks + 2 * 64 * 72;     // [2][64][72]
    __half* es = vs + 2 * 64 * 72;     // [128][72] (64 cols used)
    float* red = (float*)(es + 128 * 72);   // [128]

    const int tid = threadIdx.x, l = tid & 31, w = tid >> 5;
    const int wq = w * 16;
    const int g = l >> 2, tig = l & 3;
    const int qt = blockIdx.x, bh = bh0 + blockIdx.y, b = bh >> 3;
    const int q0 = qt * 128;

    const __half* qg = g_qh + ((size_t)bh * L_ + q0) * DH_;
    const __half* kg = g_kh + (size_t)bh * L_ * DH_;
    const __half* vg = g_vh + (size_t)bh * L_ * DH_;
    const uint8_t* mbB = (const uint8_t*)g_maskb + ((size_t)b * L_ * L_ >> 3);

    const uint32_t qs_s = (uint32_t)__cvta_generic_to_shared(qs);
    const uint32_t ks_s = (uint32_t)__cvta_generic_to_shared(ks);
    const uint32_t vs_s = (uint32_t)__cvta_generic_to_shared(vs);

#define ISSUE_K(kt_, buf_)                                                     \
    do {                                                                       \
        _Pragma("unroll")                                                      \
        for (int t = 0; t < 2; t++) {                                          \
            const int s = tid + 256 * t;                                       \
            const int r = s >> 3, c = (s & 7) << 3;                            \
            cpa16(ks_s + (uint32_t)(((buf_) * 64 * 72 + r * 72 + c) * 2),      \
                  kg + (size_t)((kt_) * 64 + r) * DH_ + c);                    \
        }                                                                      \
        cpcommit();                                                            \
    } while (0)
#define ISSUE_V(kt_, buf_)                                                     \
    do {                                                                       \
        _Pragma("unroll")                                                      \
        for (int t = 0; t < 2; t++) {                                          \
            const int s = tid + 256 * t;                                       \
            const int r = s >> 3, c = (s & 7) << 3;                            \
            cpa16(vs_s + (uint32_t)(((buf_) * 64 * 72 + r * 72 + c) * 2),      \
                  vg + (size_t)((kt_) * 64 + r) * DH_ + c);                    \
        }                                                                      \
        cpcommit();                                                            \
    } while (0)

    // Q (group), K0 (group), V0 (group)
#pragma unroll
    for (int t = 0; t < 4; t++) {
        const int s = tid + 256 * t;
        const int r = s >> 3, c = (s & 7) << 3;
        cpa16(qs_s + (uint32_t)((r * 72 + c) * 2), qg + (size_t)r * DH_ + c);
    }
    cpcommit();
    ISSUE_K(0, 0);
    ISSUE_V(0, 0);

    // ldmatrix lane addressing
    const int a_row = wq + (l & 15);
    const int a_col = (l >> 4) << 3;
    const int kb_row = ((l >> 4) << 3) + (l & 7);
    const int kb_col = ((l >> 3) & 1) << 3;
    const int vb_row = (((l >> 3) & 1) << 3) + (l & 7);
    const int vb_col = (l >> 4) << 3;

    cpwait<2>();
    __syncthreads();

    uint32_t qa[4][4];
    const uint32_t qaddr = qs_s + (uint32_t)((a_row * 72 + a_col) * 2);
#pragma unroll
    for (int kc = 0; kc < 4; kc++)
        ldsm4(qa[kc][0], qa[kc][1], qa[kc][2], qa[kc][3], qaddr + kc * 32);

    float4 ctx[8];
#pragma unroll
    for (int j = 0; j < 8; j++) ctx[j] = make_float4(0.f, 0.f, 0.f, 0.f);
    float rs0 = 0.f, rs1 = 0.f;

    const int rg0 = q0 + wq + g;
    const int rg1 = rg0 + 8;
    const int er0 = wq + g;            // local e rows
    __half* eg = g_eh + ((size_t)bh * L_ + q0) * L_;

    // mask prefetch for kt = 0
    uint64_t m0w = (*(const uint64_t*)(mbB + (size_t)rg0 * 256)) >> (2 * tig);
    uint64_t m1w = (*(const uint64_t*)(mbB + (size_t)rg1 * 256)) >> (2 * tig);

    for (int kt = 0; kt < 32; kt++) {
        const int buf = kt & 1;
        cpwait<1>();
        __syncthreads();

        // prefetch next iteration's mask words (resolve under QK MMAs)
        uint64_t n0w = 0, n1w = 0;
        if (kt + 1 < 32) {
            n0w = (*(const uint64_t*)(mbB + (size_t)rg0 * 256 + (kt + 1) * 8)) >> (2 * tig);
            n1w = (*(const uint64_t*)(mbB + (size_t)rg1 * 256 + (kt + 1) * 8)) >> (2 * tig);
        }

        // ---- QK^T ----
        float4 acc[8];
#pragma unroll
        for (int j = 0; j < 8; j++) acc[j] = make_float4(0.f, 0.f, 0.f, 0.f);

        const uint32_t ksb = ks_s + (uint32_t)(buf * 64 * 72 * 2);
#pragma unroll
        for (int kc = 0; kc < 4; kc++) {
#pragma unroll
            for (int q4 = 0; q4 < 4; q4++) {
                uint32_t b0, b1, b2, b3;
                ldsm4(b0, b1, b2, b3,
                      ksb + (uint32_t)(((q4 * 16 + kb_row) * 72 + kc * 16 + kb_col) * 2));
                mma_f16(acc[2 * q4],     qa[kc][0], qa[kc][1], qa[kc][2], qa[kc][3], b0, b1);
                mma_f16(acc[2 * q4 + 1], qa[kc][0], qa[kc][1], qa[kc][2], qa[kc][3], b2, b3);
            }
        }

        if (kt + 1 < 32) ISSUE_K(kt + 1, buf ^ 1);

        // ---- epilogue: bitmask exp2 (Q pre-scaled) -> es smem + repack ----
        uint32_t plo[8], phi[8];
#pragma unroll
        for (int j = 0; j < 8; j++) {
            const unsigned t0 = (unsigned)(m0w >> (8 * j)) & 3u;
            const unsigned t1 = (unsigned)(m1w >> (8 * j)) & 3u;
            const float e0 = (t0 & 1u) ? exp2f(acc[j].x) : 0.f;
            const float e1 = (t0 & 2u) ? exp2f(acc[j].y) : 0.f;
            const float e2 = (t1 & 1u) ? exp2f(acc[j].z) : 0.f;
            const float e3 = (t1 & 2u) ? exp2f(acc[j].w) : 0.f;
            rs0 += e0 + e1;
            rs1 += e2 + e3;
            const __half2 h0 = __floats2half2_rn(e0, e1);
            const __half2 h1 = __floats2half2_rn(e2, e3);
            plo[j] = *(const uint32_t*)&h0;
            phi[j] = *(const uint32_t*)&h1;
            const int cl = 8 * j + 2 * tig;
            *(__half2*)&es[er0 * 72 + cl] = h0;
            *(__half2*)&es[(er0 + 8) * 72 + cl] = h1;
        }
        m0w = n0w;
        m1w = n1w;

        if (kt + 1 < 32) cpwait<1>(); else cpwait<0>();
        __syncthreads();   // publishes es + vs

        // ---- coalesced e tile store FIRST (drains under PV MMAs) ----
#pragma unroll
        for (int t = 0; t < 4; t++) {
            const int s = tid + 256 * t;
            const int r = s >> 3, c = (s & 7) << 3;
            __stcs((uint4*)(eg + (size_t)r * L_ + kt * 64 + c), *(const uint4*)&es[r * 72 + c]);
        }

        // ---- P @ V (A from registers) ----
        const uint32_t vsb = vs_s + (uint32_t)(buf * 64 * 72 * 2);
#pragma unroll
        for (int kc = 0; kc < 4; kc++) {
            const uint32_t a0 = plo[2 * kc], a1 = phi[2 * kc];
            const uint32_t a2 = plo[2 * kc + 1], a3 = phi[2 * kc + 1];
#pragma unroll
            for (int q4 = 0; q4 < 4; q4++) {
                uint32_t b0, b1, b2, b3;
                ldsm4t(b0, b1, b2, b3,
                       vsb + (uint32_t)(((kc * 16 + vb_row) * 72 + q4 * 16 + vb_col) * 2));
                mma_f16(ctx[2 * q4],     a0, a1, a2, a3, b0, b1);
                mma_f16(ctx[2 * q4 + 1], a0, a1, a2, a3, b2, b3);
            }
        }

        if (kt + 1 < 32) ISSUE_V(kt + 1, buf ^ 1);
    }

    // ---- rowsum reduce -> inv ----
    rs0 += __shfl_xor_sync(0xffffffffu, rs0, 1);
    rs0 += __shfl_xor_sync(0xffffffffu, rs0, 2);
    rs1 += __shfl_xor_sync(0xffffffffu, rs1, 1);
    rs1 += __shfl_xor_sync(0xffffffffu, rs1, 2);
    if (tig == 0) {
        red[wq + g] = rs0;
        red[wq + 8 + g] = rs1;
    }
    __syncthreads();
    if (tid < 128) {
        const float s = red[tid];
        const float iv = (s > 0.f) ? (1.f / s) : 0.f;
        g_inv[(size_t)bh * L_ + q0 + tid] = iv;
        red[tid] = iv;
    }
    __syncthreads();
    const float iv0 = red[wq + g];
    const float iv1 = red[wq + 8 + g];

    // ---- ctx write (normalized fp16) ----
#pragma unroll
    for (int j = 0; j < 8; j++) {
        const int cd = 8 * j + 2 * tig;
        *(__half2*)&g_ctxh[((size_t)bh * L_ + rg0) * DH_ + cd] =
            __floats2half2_rn(ctx[j].x * iv0, ctx[j].y * iv0);
        *(__half2*)&g_ctxh[((size_t)bh * L_ + rg1) * DH_ + cd] =
            __floats2half2_rn(ctx[j].z * iv1, ctx[j].w * iv1);
    }
    (void)dummy;
#undef ISSUE_K
#undef ISSUE_V
}

// ---------------------------------------------------------------------------
// Static side stream + events for graph fork/join.
// ---------------------------------------------------------------------------
static cudaStream_t g_s2 = nullptr;
static cudaEvent_t g_evA, g_evB, g_evC, g_evD, g_evE;

extern "C" void kernel_launch(void* const* d_in, const int* in_sizes, int n_in,
                              void* d_out, int out_size) {
    const float* Q  = (const float*)d_in[0];
    const float* K  = (const float*)d_in[1];
    const float* V  = (const float*)d_in[2];
    const int*   Mk = (const int*)d_in[3];
    const float* Wq = (const float*)d_in[4];
    const float* bq = (const float*)d_in[5];
    const float* Wk = (const float*)d_in[6];
    const float* bk = (const float*)d_in[7];
    const float* Wv = (const float*)d_in[8];
    const float* bv = (const float*)d_in[9];
    const float* Wo = (const float*)d_in[10];
    const float* bo = (const float*)d_in[11];

    float* out  = (float*)d_out;
    float* attn = out + OUT_ELEMS;   // concat(out, attn_dist)

    if (!g_s2) {
        cudaStreamCreateWithFlags(&g_s2, cudaStreamNonBlocking);
        cudaEventCreateWithFlags(&g_evA, cudaEventDisableTiming);
        cudaEventCreateWithFlags(&g_evB, cudaEventDisableTiming);
        cudaEventCreateWithFlags(&g_evC, cudaEventDisableTiming);
        cudaEventCreateWithFlags(&g_evD, cudaEventDisableTiming);
        cudaEventCreateWithFlags(&g_evE, cudaEventDisableTiming);
    }

    const int smem_gemm = (3 * 128 * 72 + 3 * 64 * 72) * 2;                  // 82944
    const int smem_attn = (128 * 72 + 4 * 64 * 72 + 128 * 72) * 2 + 128 * 4; // 74240
    cudaFuncSetAttribute(proj3, cudaFuncAttributeMaxDynamicSharedMemorySize, smem_gemm);
    cudaFuncSetAttribute(out_gemm, cudaFuncAttributeMaxDynamicSharedMemorySize, smem_gemm);
    cudaFuncSetAttribute(attn_fp16, cudaFuncAttributeMaxDynamicSharedMemorySize, smem_attn);

    // ---- fork 1: mask bitpack on side stream, converts+proj on main ----
    cudaEventRecord(g_evA, 0);
    cudaStreamWaitEvent(g_s2, g_evA, 0);
    pack_mask<<<2048, 256, 0, g_s2>>>(Mk);
    cudaEventRecord(g_evB, g_s2);

    convert_f2h<<<3 * 4096 + 4 * 256, 256>>>(Q, K, V, Wq, Wk, Wv, Wo);
    proj3<<<dim3(8, 64, 3), 256, smem_gemm>>>(bq, bk, bv);

    cudaStreamWaitEvent(0, g_evB, 0);   // join: attn needs mask + projections

    const dim3 gah(16, 16);   // q-tiles of 128, 16 heads per half

    // ---- attn half A (bh 0..15) on main ----
    attn_fp16<<<gah, 256, smem_attn>>>(attn, 0);

    // ---- fork 2: rescale half A on side stream, attn half B on main ----
    cudaEventRecord(g_evC, 0);
    cudaStreamWaitEvent(g_s2, g_evC, 0);
    rescale_attn<<<16384, 256, 0, g_s2>>>(attn, 0);

    attn_fp16<<<gah, 256, smem_attn>>>(attn, 16);
    cudaEventRecord(g_evD, 0);          // attn B done (ctx complete)

    // ---- out_gemm on side stream (after rescaleA in program order + attnB);
    //      rescale half B on main ----
    cudaStreamWaitEvent(g_s2, g_evD, 0);
    out_gemm<<<dim3(8, 64), 256, smem_gemm, g_s2>>>(bo, out);
    cudaEventRecord(g_evE, g_s2);

    rescale_attn<<<16384, 256>>>(attn, 32768);

    cudaStreamWaitEvent(0, g_evE, 0);   // join before harness sync
}